// round 1
// baseline (speedup 1.0000x reference)
#include <cuda_runtime.h>
#include <math.h>

#define B_   4
#define S_   2048
#define DIN  1024
#define H_   16
#define DH   64
#define M_   (B_ * S_)       // 8192
#define NQKV (3 * H_ * DH)   // 3072

// ---- scratch (device globals: allocation-free) ----
__device__ float g_q[B_ * H_ * S_ * DH];   // [B,H,S,DH]
__device__ float g_k[B_ * H_ * S_ * DH];
__device__ float g_v[B_ * H_ * S_ * DH];
__device__ float g_att[M_ * H_ * DH];      // [B*S, H*DH] (concat layout)

// ============================================================================
// Kernel 1: fused QKV projection.
// C[8192, 3072] = X[8192,1024] @ [Wq|Wk|Wv], +bias, scattered to g_q/g_k/g_v
// in [B,H,S,DH] layout. 128x128 tiles, BK=8, 8x8 register microtiles.
// ============================================================================
__global__ __launch_bounds__(256) void qkv_kernel(
    const float* __restrict__ x,
    const float* __restrict__ Wq, const float* __restrict__ bq,
    const float* __restrict__ Wk, const float* __restrict__ bk,
    const float* __restrict__ Wv, const float* __restrict__ bv)
{
    __shared__ float Xts[8][132];   // K-major (transposed) X tile, padded
    __shared__ float Ws[8][128];    // W tile

    const int bm = blockIdx.x;          // 0..63  (128 rows each)
    const int bn = blockIdx.y;          // 0..23  (128 cols each)
    const int tid = threadIdx.x;
    const int tx = tid & 15, ty = tid >> 4;
    const int ty4 = ty * 4, tx4 = tx * 4;

    const int part = bn >> 3;           // 0=Q,1=K,2=V (1024/128 = 8 blocks/part)
    const int w0 = (bn & 7) << 7;       // column offset within part

    const float* __restrict__ Wp = (part == 0) ? Wq : (part == 1) ? Wk : Wv;
    const float* __restrict__ bp = (part == 0) ? bq : (part == 1) ? bk : bv;
    float* __restrict__ outp     = (part == 0) ? g_q : (part == 1) ? g_k : g_v;

    // loader indices
    const int lxr = tid >> 1;               // 0..127
    const int lxk = (tid & 1) << 2;         // 0 or 4
    const int lwr = tid >> 5;               // 0..7
    const int lwc = (tid & 31) << 2;        // 0..124
    const int wcol = w0 + lwc;
    const int lh = wcol >> 6, le = wcol & 63;

    float acc[8][8];
#pragma unroll
    for (int i = 0; i < 8; i++)
#pragma unroll
        for (int j = 0; j < 8; j++) acc[i][j] = 0.0f;

    for (int k0 = 0; k0 < DIN; k0 += 8) {
        float4 xa = *(const float4*)&x[(bm * 128 + lxr) * DIN + k0 + lxk];
        float4 wa = *(const float4*)&Wp[lh * (DIN * DH) + (k0 + lwr) * DH + le];
        __syncthreads();
        Xts[lxk + 0][lxr] = xa.x;
        Xts[lxk + 1][lxr] = xa.y;
        Xts[lxk + 2][lxr] = xa.z;
        Xts[lxk + 3][lxr] = xa.w;
        *(float4*)&Ws[lwr][lwc] = wa;
        __syncthreads();

#pragma unroll
        for (int kk = 0; kk < 8; kk++) {
            float4 a0 = *(const float4*)&Xts[kk][ty4];
            float4 a1 = *(const float4*)&Xts[kk][64 + ty4];
            float4 b0 = *(const float4*)&Ws[kk][tx4];
            float4 b1 = *(const float4*)&Ws[kk][64 + tx4];
            float a[8] = {a0.x, a0.y, a0.z, a0.w, a1.x, a1.y, a1.z, a1.w};
            float bb[8] = {b0.x, b0.y, b0.z, b0.w, b1.x, b1.y, b1.z, b1.w};
#pragma unroll
            for (int i = 0; i < 8; i++)
#pragma unroll
                for (int j = 0; j < 8; j++) acc[i][j] += a[i] * bb[j];
        }
    }

    // epilogue: scatter to [B,H,S,DH] with bias
#pragma unroll
    for (int ii = 0; ii < 8; ii++) {
        int r = (ii < 4) ? (ty4 + ii) : (64 + ty4 + ii - 4);
        int m = bm * 128 + r;
        int b = m >> 11, s = m & 2047;
#pragma unroll
        for (int jj = 0; jj < 8; jj++) {
            int cc = (jj < 4) ? (tx4 + jj) : (64 + tx4 + jj - 4);
            int w = w0 + cc;
            int h = w >> 6, e = w & 63;
            outp[((b * H_ + h) * S_ + s) * DH + e] = acc[ii][jj] + bp[h * DH + e];
        }
    }
}

// ============================================================================
// Kernel 2: causal flash attention, fp32, exp2-domain online softmax.
// One block per (qtile=64 rows, h, b). 64x64 tiles, 4x4 microtiles.
// Q/K stored transposed (e-major) in smem so all inner loops are float4 LDS.
// ============================================================================
__global__ __launch_bounds__(256) void attn_kernel()
{
    extern __shared__ float sm[];
    float* Qts = sm;                 // [64][68], Qts[e*68 + r], pre-scaled
    float* Kts = sm + 64 * 68;       // [64][68], Kts[e*68 + r]
    float* Pts = sm + 2 * 64 * 68;   // [64][68], Pts[k*68 + r]
    float* Vs  = sm + 3 * 64 * 68;   // [64][64] row-major

    const int qt = blockIdx.x, h = blockIdx.y, b = blockIdx.z;
    const int tid = threadIdx.x;
    const int tx = tid & 15, ty = tid >> 4;
    const int ty4 = ty * 4, tx4 = tx * 4;

    const int bh = (b * H_ + h) * S_;
    const float* __restrict__ qptr = g_q + bh * DH;
    const float* __restrict__ kptr = g_k + bh * DH;
    const float* __restrict__ vptr = g_v + bh * DH;

    const float SCALE = 0.125f * 1.44269504088896340736f;  // (1/sqrt(64)) * log2(e)

    // load Q tile transposed + pre-scaled (once)
    for (int i = tid; i < 64 * 64; i += 256) {
        int r = i >> 6, e = i & 63;
        Qts[e * 68 + r] = qptr[(qt * 64 + r) * DH + e] * SCALE;
    }

    float acc[4][4];
#pragma unroll
    for (int i = 0; i < 4; i++)
#pragma unroll
        for (int j = 0; j < 4; j++) acc[i][j] = 0.0f;
    float mrow[4] = {-INFINITY, -INFINITY, -INFINITY, -INFINITY};
    float lrow[4] = {0.0f, 0.0f, 0.0f, 0.0f};

    for (int kt = 0; kt <= qt; kt++) {
        __syncthreads();  // protect Kts/Vs/Pts from previous iteration readers
        for (int i = tid; i < 64 * 64; i += 256) {
            int r = i >> 6, e = i & 63;
            Kts[e * 68 + r] = kptr[(kt * 64 + r) * DH + e];
        }
        for (int i = tid; i < 64 * 16; i += 256) {
            int r = i >> 4, c = (i & 15) << 2;
            *(float4*)&Vs[r * 64 + c] = *(const float4*)&vptr[(kt * 64 + r) * DH + c];
        }
        __syncthreads();

        // S = Q K^T (already in log2 domain via pre-scaled Q)
        float s[4][4];
#pragma unroll
        for (int i = 0; i < 4; i++)
#pragma unroll
            for (int j = 0; j < 4; j++) s[i][j] = 0.0f;
#pragma unroll 8
        for (int e = 0; e < 64; e++) {
            float4 a = *(const float4*)&Qts[e * 68 + ty4];
            float4 bb = *(const float4*)&Kts[e * 68 + tx4];
            float av[4] = {a.x, a.y, a.z, a.w};
            float bv[4] = {bb.x, bb.y, bb.z, bb.w};
#pragma unroll
            for (int i = 0; i < 4; i++)
#pragma unroll
                for (int j = 0; j < 4; j++) s[i][j] += av[i] * bv[j];
        }

        if (kt == qt) {  // diagonal tile: causal mask
#pragma unroll
            for (int i = 0; i < 4; i++)
#pragma unroll
                for (int j = 0; j < 4; j++)
                    if (tx4 + j > ty4 + i) s[i][j] = -1e30f;
        }

        // online softmax (exp2 domain)
#pragma unroll
        for (int i = 0; i < 4; i++) {
            float tm = fmaxf(fmaxf(s[i][0], s[i][1]), fmaxf(s[i][2], s[i][3]));
#pragma unroll
            for (int off = 1; off < 16; off <<= 1)
                tm = fmaxf(tm, __shfl_xor_sync(0xffffffffu, tm, off));
            float mn = fmaxf(mrow[i], tm);
            float al = exp2f(mrow[i] - mn);
            float rs = 0.0f;
#pragma unroll
            for (int j = 0; j < 4; j++) {
                s[i][j] = exp2f(s[i][j] - mn);
                rs += s[i][j];
            }
#pragma unroll
            for (int off = 1; off < 16; off <<= 1)
                rs += __shfl_xor_sync(0xffffffffu, rs, off);
            lrow[i] = lrow[i] * al + rs;
            mrow[i] = mn;
#pragma unroll
            for (int j = 0; j < 4; j++) acc[i][j] *= al;
            // store P transposed: Pts[key][row]
#pragma unroll
            for (int j = 0; j < 4; j++)
                Pts[(tx4 + j) * 68 + ty4 + i] = s[i][j];
        }
        __syncthreads();

        // O += P V
#pragma unroll 4
        for (int k = 0; k < 64; k++) {
            float4 a = *(const float4*)&Pts[k * 68 + ty4];
            float4 v = *(const float4*)&Vs[k * 64 + tx4];
            float av[4] = {a.x, a.y, a.z, a.w};
            float vv[4] = {v.x, v.y, v.z, v.w};
#pragma unroll
            for (int i = 0; i < 4; i++)
#pragma unroll
                for (int j = 0; j < 4; j++) acc[i][j] += av[i] * vv[j];
        }
    }

    // write to concat layout [B*S, H*DH]
    const int HD = H_ * DH;
    int row0 = b * S_ + qt * 64;
#pragma unroll
    for (int i = 0; i < 4; i++) {
        float inv = 1.0f / lrow[i];
#pragma unroll
        for (int j = 0; j < 4; j++)
            g_att[(row0 + ty4 + i) * HD + h * DH + tx4 + j] = acc[i][j] * inv;
    }
}

// ============================================================================
// Kernel 3: output projection. out[8192,64] = g_att[8192,1024] @ Wo + bo
// ============================================================================
__global__ __launch_bounds__(256) void oproj_kernel(
    const float* __restrict__ Wo, const float* __restrict__ bo,
    float* __restrict__ out)
{
    __shared__ float Ats[16][68];
    __shared__ float Ws2[16][64];

    const int m0 = blockIdx.x * 64;
    const int tid = threadIdx.x;
    const int tx = tid & 15, ty = tid >> 4;
    const int ty4 = ty * 4, tx4 = tx * 4;

    float acc[4][4];
#pragma unroll
    for (int i = 0; i < 4; i++)
#pragma unroll
        for (int j = 0; j < 4; j++) acc[i][j] = 0.0f;

    for (int k0 = 0; k0 < DIN; k0 += 16) {
        __syncthreads();
        for (int i = tid; i < 64 * 16; i += 256) {
            int r = i >> 4, kc = i & 15;
            Ats[kc][r] = g_att[(m0 + r) * DIN + k0 + kc];
        }
        for (int i = tid; i < 16 * 64; i += 256) {
            int kk = i >> 6, n = i & 63;
            Ws2[kk][n] = Wo[(k0 + kk) * DH + n];
        }
        __syncthreads();

#pragma unroll
        for (int kk = 0; kk < 16; kk++) {
            float4 a = *(const float4*)&Ats[kk][ty4];
            float4 w = *(const float4*)&Ws2[kk][tx4];
            float av[4] = {a.x, a.y, a.z, a.w};
            float wv[4] = {w.x, w.y, w.z, w.w};
#pragma unroll
            for (int i = 0; i < 4; i++)
#pragma unroll
                for (int j = 0; j < 4; j++) acc[i][j] += av[i] * wv[j];
        }
    }

#pragma unroll
    for (int i = 0; i < 4; i++)
#pragma unroll
        for (int j = 0; j < 4; j++)
            out[(m0 + ty4 + i) * DH + tx4 + j] = acc[i][j] + bo[tx4 + j];
}

// ============================================================================
extern "C" void kernel_launch(void* const* d_in, const int* in_sizes, int n_in,
                              void* d_out, int out_size)
{
    const float* x  = (const float*)d_in[0];
    const float* Wq = (const float*)d_in[1];
    const float* bq = (const float*)d_in[2];
    const float* Wk = (const float*)d_in[3];
    const float* bk = (const float*)d_in[4];
    const float* Wv = (const float*)d_in[5];
    const float* bv = (const float*)d_in[6];
    const float* Wo = (const float*)d_in[7];
    const float* bo = (const float*)d_in[8];
    float* out = (float*)d_out;

    // attention dynamic smem: (3*64*68 + 64*64) floats = 68608 bytes
    cudaFuncSetAttribute(attn_kernel, cudaFuncAttributeMaxDynamicSharedMemorySize,
                         68608);

    qkv_kernel<<<dim3(64, 24), 256>>>(x, Wq, bq, Wk, bk, Wv, bv);
    attn_kernel<<<dim3(S_ / 64, H_, B_), 256, 68608>>>();
    oproj_kernel<<<M_ / 64, 256>>>(Wo, bo, out);
}

// round 3
// speedup vs baseline: 1.3137x; 1.3137x over previous
#include <cuda_runtime.h>
#include <cuda_bf16.h>
#include <math.h>
#include <stdint.h>

#define B_   4
#define S_   2048
#define DIN  1024
#define H_   16
#define DH   64
#define M_   (B_ * S_)       // 8192
#define NTOT 3072

// ---- scratch (device globals: allocation-free) ----
__device__ float g_q[B_ * H_ * S_ * DH];   // [B,H,S,DH]
__device__ float g_k[B_ * H_ * S_ * DH];
__device__ float g_v[B_ * H_ * S_ * DH];
__device__ float g_att[M_ * H_ * DH];      // [B*S, H*DH]

// bf16 split operands for QKV GEMM
__device__ __nv_bfloat16 g_xhi[M_ * DIN];      // [8192][1024] K-contig
__device__ __nv_bfloat16 g_xlo[M_ * DIN];
__device__ __nv_bfloat16 g_whi[NTOT * DIN];    // [3072][1024] K-contig (B[n][k])
__device__ __nv_bfloat16 g_wlo[NTOT * DIN];

// ============================================================================
// helpers
// ============================================================================
__device__ __forceinline__ uint32_t smem_u32(const void* p) {
    uint32_t a;
    asm("{ .reg .u64 t; cvta.to.shared.u64 t, %1; cvt.u32.u64 %0, t; }"
        : "=r"(a) : "l"(p));
    return a;
}
__device__ __forceinline__ void cp16(uint32_t dst, const void* src) {
    asm volatile("cp.async.cg.shared.global [%0], [%1], 16;" :: "r"(dst), "l"(src));
}
#define CP_COMMIT() asm volatile("cp.async.commit_group;" ::: "memory")
#define CP_WAIT(n)  asm volatile("cp.async.wait_group %0;" :: "n"(n) : "memory")

__device__ __forceinline__ void ldsm_x4(uint32_t* r, uint32_t addr) {
    asm volatile("ldmatrix.sync.aligned.m8n8.x4.shared.b16 {%0,%1,%2,%3}, [%4];"
                 : "=r"(r[0]), "=r"(r[1]), "=r"(r[2]), "=r"(r[3]) : "r"(addr));
}
__device__ __forceinline__ void mma_bf16(float* c, const uint32_t* a, const uint32_t* b) {
    asm volatile(
        "mma.sync.aligned.m16n8k16.row.col.f32.bf16.bf16.f32 "
        "{%0,%1,%2,%3}, {%4,%5,%6,%7}, {%8,%9}, {%0,%1,%2,%3};"
        : "+f"(c[0]), "+f"(c[1]), "+f"(c[2]), "+f"(c[3])
        : "r"(a[0]), "r"(a[1]), "r"(a[2]), "r"(a[3]), "r"(b[0]), "r"(b[1]));
}

// ============================================================================
// bf16 hi/lo split conversion kernels
// ============================================================================
__global__ __launch_bounds__(256) void cvt_x_kernel(const float* __restrict__ x) {
    int i = (blockIdx.x * 256 + threadIdx.x) * 4;
    float4 v = *(const float4*)&x[i];
    float vv[4] = {v.x, v.y, v.z, v.w};
#pragma unroll
    for (int j = 0; j < 4; j++) {
        __nv_bfloat16 hi = __float2bfloat16_rn(vv[j]);
        __nv_bfloat16 lo = __float2bfloat16_rn(vv[j] - __bfloat162float(hi));
        g_xhi[i + j] = hi;
        g_xlo[i + j] = lo;
    }
}

__global__ __launch_bounds__(256) void cvt_w_kernel(
    const float* __restrict__ Wq, const float* __restrict__ Wk,
    const float* __restrict__ Wv) {
    int t = blockIdx.x * 256 + threadIdx.x;
    int part = t >> 20;
    int rem = t & 1048575;
    int h = rem >> 16;
    int k = (rem >> 6) & 1023;
    int e = rem & 63;
    const float* Wp = (part == 0) ? Wq : (part == 1) ? Wk : Wv;
    float v = Wp[h * (DIN * DH) + k * DH + e];
    __nv_bfloat16 hi = __float2bfloat16_rn(v);
    __nv_bfloat16 lo = __float2bfloat16_rn(v - __bfloat162float(hi));
    int n = part * 1024 + h * 64 + e;
    g_whi[(size_t)n * DIN + k] = hi;
    g_wlo[(size_t)n * DIN + k] = lo;
}

// ============================================================================
// QKV GEMM via mma.sync bf16 (3-pass split, fused in k-loop).
// C[8192,3072] = X @ W + bias -> scatter to g_q/g_k/g_v [B,H,S,DH].
// 128x128 tile, BK=32, 8 warps (2m x 4n), warp tile 64x32.
// smem rows padded to 40 bf16 (80B) -> conflict-free ldmatrix.
// ============================================================================
#define BK      32
#define NCHUNK  (DIN / BK)        // 32
#define ROWB    80                // bytes per padded row
#define A_HI    0
#define A_LO    10240
#define B_HI    20480
#define B_LO    30720
#define STAGE_B 40960

__global__ __launch_bounds__(256) void qkv_mma_kernel(
    const float* __restrict__ bq, const float* __restrict__ bk,
    const float* __restrict__ bv)
{
    extern __shared__ __align__(128) char smem[];
    const uint32_t sb0 = smem_u32(smem);
    const int tid = threadIdx.x;
    const int wid = tid >> 5, l = tid & 31;
    const int wm = wid & 1, wn = wid >> 1;      // 2 x 4 warp grid
    const int bm = blockIdx.x;                  // 64 blocks of 128 rows
    const int bn = blockIdx.y;                  // 24 blocks of 128 cols

    const int arow0 = bm * 128, brow0 = bn * 128;

    // per-lane ldmatrix byte offsets (within a stage's A or B region)
    uint32_t aoff[4], boff[2];
#pragma unroll
    for (int mi = 0; mi < 4; mi++) {
        int row = wm * 64 + mi * 16 + (l & 7) + ((l >> 3) & 1) * 8;
        int col = ((l >> 4) & 1) * 8;
        aoff[mi] = (uint32_t)(row * ROWB + col * 2);
    }
#pragma unroll
    for (int bg = 0; bg < 2; bg++) {
        int nrow = wn * 32 + bg * 16 + ((l >> 4) & 1) * 8 + (l & 7);
        int col = ((l >> 3) & 1) * 8;
        boff[bg] = (uint32_t)(nrow * ROWB + col * 2);
    }

    float acc[4][4][4];
#pragma unroll
    for (int i = 0; i < 4; i++)
#pragma unroll
        for (int j = 0; j < 4; j++)
#pragma unroll
            for (int q = 0; q < 4; q++) acc[i][j][q] = 0.0f;

    // chunk loader: 8 cp.async x16B per thread per array-pair set
    auto load_chunk = [&](int c, int s) {
        uint32_t base = sb0 + (uint32_t)s * STAGE_B;
#pragma unroll
        for (int i = 0; i < 2; i++) {
            int slot = tid + i * 256;          // 0..511
            int row = slot >> 2, kg = slot & 3;
            uint32_t so = (uint32_t)(row * ROWB + kg * 16);
            size_t goA = (size_t)(arow0 + row) * DIN + c * BK + kg * 8;
            size_t goB = (size_t)(brow0 + row) * DIN + c * BK + kg * 8;
            cp16(base + A_HI + so, g_xhi + goA);
            cp16(base + A_LO + so, g_xlo + goA);
            cp16(base + B_HI + so, g_whi + goB);
            cp16(base + B_LO + so, g_wlo + goB);
        }
    };

    load_chunk(0, 0);
    CP_COMMIT();
    load_chunk(1, 1);
    CP_COMMIT();

    for (int c = 0; c < NCHUNK; c++) {
        int s = c & 1;
        if (c >= NCHUNK - 2) { CP_WAIT(0); } else { CP_WAIT(1); }
        __syncthreads();

        uint32_t base = sb0 + (uint32_t)s * STAGE_B;
#pragma unroll
        for (int ks = 0; ks < 2; ks++) {
            uint32_t kadd = (uint32_t)(ks * 32);   // 16 bf16 cols
            uint32_t ahi[4][4], alo[4][4], bhi[4][2], blo[4][2];
#pragma unroll
            for (int mi = 0; mi < 4; mi++) {
                ldsm_x4(ahi[mi], base + A_HI + aoff[mi] + kadd);
                ldsm_x4(alo[mi], base + A_LO + aoff[mi] + kadd);
            }
#pragma unroll
            for (int bg = 0; bg < 2; bg++) {
                uint32_t r[4];
                ldsm_x4(r, base + B_HI + boff[bg] + kadd);
                bhi[bg * 2][0] = r[0]; bhi[bg * 2][1] = r[1];
                bhi[bg * 2 + 1][0] = r[2]; bhi[bg * 2 + 1][1] = r[3];
                ldsm_x4(r, base + B_LO + boff[bg] + kadd);
                blo[bg * 2][0] = r[0]; blo[bg * 2][1] = r[1];
                blo[bg * 2 + 1][0] = r[2]; blo[bg * 2 + 1][1] = r[3];
            }
#pragma unroll
            for (int mi = 0; mi < 4; mi++)
#pragma unroll
                for (int ni = 0; ni < 4; ni++) {
                    mma_bf16(acc[mi][ni], ahi[mi], bhi[ni]);
                    mma_bf16(acc[mi][ni], ahi[mi], blo[ni]);
                    mma_bf16(acc[mi][ni], alo[mi], bhi[ni]);
                }
        }

        __syncthreads();   // all warps done reading stage s
        if (c + 2 < NCHUNK) {
            load_chunk(c + 2, s);
            CP_COMMIT();
        }
    }

    // epilogue: direct scatter to [B,H,S,DH] with bias, 8B stores
    const int part = bn >> 3;
    const float* __restrict__ bp = (part == 0) ? bq : (part == 1) ? bk : bv;
    float* __restrict__ op      = (part == 0) ? g_q : (part == 1) ? g_k : g_v;
    const int npart0 = (bn & 7) * 128 + wn * 32;

#pragma unroll
    for (int mi = 0; mi < 4; mi++) {
        int m0 = arow0 + wm * 64 + mi * 16 + (l >> 2);
#pragma unroll
        for (int ni = 0; ni < 4; ni++) {
            int ncol = npart0 + ni * 8 + 2 * (l & 3);
            int h = ncol >> 6, e = ncol & 63;
            float b0 = bp[h * DH + e], b1 = bp[h * DH + e + 1];
#pragma unroll
            for (int half = 0; half < 2; half++) {
                int m = m0 + half * 8;
                int bb = m >> 11, sIdx = m & 2047;
                float2 v;
                v.x = acc[mi][ni][half * 2 + 0] + b0;
                v.y = acc[mi][ni][half * 2 + 1] + b1;
                *(float2*)&op[(((size_t)bb * H_ + h) * S_ + sIdx) * DH + e] = v;
            }
        }
    }
}

// ============================================================================
// Kernel 2: causal flash attention, fp32 (unchanged — known correct)
// ============================================================================
__global__ __launch_bounds__(256) void attn_kernel()
{
    extern __shared__ float sm[];
    float* Qts = sm;
    float* Kts = sm + 64 * 68;
    float* Pts = sm + 2 * 64 * 68;
    float* Vs  = sm + 3 * 64 * 68;

    const int qt = blockIdx.x, h = blockIdx.y, b = blockIdx.z;
    const int tid = threadIdx.x;
    const int tx = tid & 15, ty = tid >> 4;
    const int ty4 = ty * 4, tx4 = tx * 4;

    const int bh = (b * H_ + h) * S_;
    const float* __restrict__ qptr = g_q + (size_t)bh * DH;
    const float* __restrict__ kptr = g_k + (size_t)bh * DH;
    const float* __restrict__ vptr = g_v + (size_t)bh * DH;

    const float SCALE = 0.125f * 1.44269504088896340736f;

    for (int i = tid; i < 64 * 64; i += 256) {
        int r = i >> 6, e = i & 63;
        Qts[e * 68 + r] = qptr[(qt * 64 + r) * DH + e] * SCALE;
    }

    float acc[4][4];
#pragma unroll
    for (int i = 0; i < 4; i++)
#pragma unroll
        for (int j = 0; j < 4; j++) acc[i][j] = 0.0f;
    float mrow[4] = {-INFINITY, -INFINITY, -INFINITY, -INFINITY};
    float lrow[4] = {0.0f, 0.0f, 0.0f, 0.0f};

    for (int kt = 0; kt <= qt; kt++) {
        __syncthreads();
        for (int i = tid; i < 64 * 64; i += 256) {
            int r = i >> 6, e = i & 63;
            Kts[e * 68 + r] = kptr[(kt * 64 + r) * DH + e];
        }
        for (int i = tid; i < 64 * 16; i += 256) {
            int r = i >> 4, c = (i & 15) << 2;
            *(float4*)&Vs[r * 64 + c] = *(const float4*)&vptr[(kt * 64 + r) * DH + c];
        }
        __syncthreads();

        float s[4][4];
#pragma unroll
        for (int i = 0; i < 4; i++)
#pragma unroll
            for (int j = 0; j < 4; j++) s[i][j] = 0.0f;
#pragma unroll 8
        for (int e = 0; e < 64; e++) {
            float4 a = *(const float4*)&Qts[e * 68 + ty4];
            float4 bb = *(const float4*)&Kts[e * 68 + tx4];
            float av[4] = {a.x, a.y, a.z, a.w};
            float bv2[4] = {bb.x, bb.y, bb.z, bb.w};
#pragma unroll
            for (int i = 0; i < 4; i++)
#pragma unroll
                for (int j = 0; j < 4; j++) s[i][j] += av[i] * bv2[j];
        }

        if (kt == qt) {
#pragma unroll
            for (int i = 0; i < 4; i++)
#pragma unroll
                for (int j = 0; j < 4; j++)
                    if (tx4 + j > ty4 + i) s[i][j] = -1e30f;
        }

#pragma unroll
        for (int i = 0; i < 4; i++) {
            float tm = fmaxf(fmaxf(s[i][0], s[i][1]), fmaxf(s[i][2], s[i][3]));
#pragma unroll
            for (int off = 1; off < 16; off <<= 1)
                tm = fmaxf(tm, __shfl_xor_sync(0xffffffffu, tm, off));
            float mn = fmaxf(mrow[i], tm);
            float al = exp2f(mrow[i] - mn);
            float rs = 0.0f;
#pragma unroll
            for (int j = 0; j < 4; j++) {
                s[i][j] = exp2f(s[i][j] - mn);
                rs += s[i][j];
            }
#pragma unroll
            for (int off = 1; off < 16; off <<= 1)
                rs += __shfl_xor_sync(0xffffffffu, rs, off);
            lrow[i] = lrow[i] * al + rs;
            mrow[i] = mn;
#pragma unroll
            for (int j = 0; j < 4; j++) acc[i][j] *= al;
#pragma unroll
            for (int j = 0; j < 4; j++)
                Pts[(tx4 + j) * 68 + ty4 + i] = s[i][j];
        }
        __syncthreads();

#pragma unroll 4
        for (int k = 0; k < 64; k++) {
            float4 a = *(const float4*)&Pts[k * 68 + ty4];
            float4 v = *(const float4*)&Vs[k * 64 + tx4];
            float av[4] = {a.x, a.y, a.z, a.w};
            float vv[4] = {v.x, v.y, v.z, v.w};
#pragma unroll
            for (int i = 0; i < 4; i++)
#pragma unroll
                for (int j = 0; j < 4; j++) acc[i][j] += av[i] * vv[j];
        }
    }

    const int HD = H_ * DH;
    int row0 = b * S_ + qt * 64;
#pragma unroll
    for (int i = 0; i < 4; i++) {
        float inv = 1.0f / lrow[i];
#pragma unroll
        for (int j = 0; j < 4; j++)
            g_att[(size_t)(row0 + ty4 + i) * HD + h * DH + tx4 + j] = acc[i][j] * inv;
    }
}

// ============================================================================
// Kernel 3: output projection (unchanged)
// ============================================================================
__global__ __launch_bounds__(256) void oproj_kernel(
    const float* __restrict__ Wo, const float* __restrict__ bo,
    float* __restrict__ out)
{
    __shared__ float Ats[16][68];
    __shared__ float Ws2[16][64];

    const int m0 = blockIdx.x * 64;
    const int tid = threadIdx.x;
    const int tx = tid & 15, ty = tid >> 4;
    const int ty4 = ty * 4, tx4 = tx * 4;

    float acc[4][4];
#pragma unroll
    for (int i = 0; i < 4; i++)
#pragma unroll
        for (int j = 0; j < 4; j++) acc[i][j] = 0.0f;

    for (int k0 = 0; k0 < DIN; k0 += 16) {
        __syncthreads();
        for (int i = tid; i < 64 * 16; i += 256) {
            int r = i >> 4, kc = i & 15;
            Ats[kc][r] = g_att[(size_t)(m0 + r) * DIN + k0 + kc];
        }
        for (int i = tid; i < 16 * 64; i += 256) {
            int kk = i >> 6, n = i & 63;
            Ws2[kk][n] = Wo[(k0 + kk) * DH + n];
        }
        __syncthreads();

#pragma unroll
        for (int kk = 0; kk < 16; kk++) {
            float4 a = *(const float4*)&Ats[kk][ty4];
            float4 w = *(const float4*)&Ws2[kk][tx4];
            float av[4] = {a.x, a.y, a.z, a.w};
            float wv[4] = {w.x, w.y, w.z, w.w};
#pragma unroll
            for (int i = 0; i < 4; i++)
#pragma unroll
                for (int j = 0; j < 4; j++) acc[i][j] += av[i] * wv[j];
        }
    }

#pragma unroll
    for (int i = 0; i < 4; i++)
#pragma unroll
        for (int j = 0; j < 4; j++)
            out[(size_t)(m0 + ty4 + i) * DH + tx4 + j] = acc[i][j] + bo[tx4 + j];
}

// ============================================================================
extern "C" void kernel_launch(void* const* d_in, const int* in_sizes, int n_in,
                              void* d_out, int out_size)
{
    const float* x  = (const float*)d_in[0];
    const float* Wq = (const float*)d_in[1];
    const float* bq = (const float*)d_in[2];
    const float* Wk = (const float*)d_in[3];
    const float* bk = (const float*)d_in[4];
    const float* Wv = (const float*)d_in[5];
    const float* bv = (const float*)d_in[6];
    const float* Wo = (const float*)d_in[7];
    const float* bo = (const float*)d_in[8];
    float* out = (float*)d_out;

    cudaFuncSetAttribute(attn_kernel, cudaFuncAttributeMaxDynamicSharedMemorySize, 68608);
    cudaFuncSetAttribute(qkv_mma_kernel, cudaFuncAttributeMaxDynamicSharedMemorySize,
                         2 * STAGE_B);

    cvt_x_kernel<<<8192, 256>>>(x);
    cvt_w_kernel<<<12288, 256>>>(Wq, Wk, Wv);
    qkv_mma_kernel<<<dim3(64, 24), 256, 2 * STAGE_B>>>(bq, bk, bv);
    attn_kernel<<<dim3(S_ / 64, H_, B_), 256, 68608>>>();
    oproj_kernel<<<M_ / 64, 256>>>(Wo, bo, out);
}

// round 4
// speedup vs baseline: 2.2711x; 1.7289x over previous
#include <cuda_runtime.h>
#include <cuda_bf16.h>
#include <math.h>
#include <stdint.h>

#define B_   4
#define S_   2048
#define DIN  1024
#define H_   16
#define DH   64
#define M_   (B_ * S_)       // 8192
#define NTOT 3072
#define BH_  (B_ * H_)       // 64

// ---- scratch (device globals: allocation-free) ----
__device__ float g_v[BH_ * S_ * DH];       // fp32 V (input to transpose)
__device__ float g_att[M_ * H_ * DH];      // [B*S, H*DH]

// split bf16 attention operands
__device__ __nv_bfloat16 a_qhi[BH_ * S_ * DH];   // [bh][s][e], pre-scaled
__device__ __nv_bfloat16 a_qlo[BH_ * S_ * DH];
__device__ __nv_bfloat16 a_khi[BH_ * S_ * DH];
__device__ __nv_bfloat16 a_klo[BH_ * S_ * DH];
__device__ __nv_bfloat16 a_vthi[BH_ * DH * S_]; // [bh][e][s]
__device__ __nv_bfloat16 a_vtlo[BH_ * DH * S_];

// bf16 split operands for QKV GEMM
__device__ __nv_bfloat16 g_xhi[M_ * DIN];
__device__ __nv_bfloat16 g_xlo[M_ * DIN];
__device__ __nv_bfloat16 g_whi[NTOT * DIN];
__device__ __nv_bfloat16 g_wlo[NTOT * DIN];

#define SCALE_LOG2E 0.18033688011112042591999058f  // 0.125 * log2(e)

// ============================================================================
// helpers
// ============================================================================
__device__ __forceinline__ uint32_t smem_u32(const void* p) {
    uint32_t a;
    asm("{ .reg .u64 t; cvta.to.shared.u64 t, %1; cvt.u32.u64 %0, t; }"
        : "=r"(a) : "l"(p));
    return a;
}
__device__ __forceinline__ void cp16(uint32_t dst, const void* src) {
    asm volatile("cp.async.cg.shared.global [%0], [%1], 16;" :: "r"(dst), "l"(src));
}
#define CP_COMMIT() asm volatile("cp.async.commit_group;" ::: "memory")
#define CP_WAIT(n)  asm volatile("cp.async.wait_group %0;" :: "n"(n) : "memory")

__device__ __forceinline__ void ldsm_x4(uint32_t* r, uint32_t addr) {
    asm volatile("ldmatrix.sync.aligned.m8n8.x4.shared.b16 {%0,%1,%2,%3}, [%4];"
                 : "=r"(r[0]), "=r"(r[1]), "=r"(r[2]), "=r"(r[3]) : "r"(addr));
}
__device__ __forceinline__ void mma_bf16(float* c, const uint32_t* a, const uint32_t* b) {
    asm volatile(
        "mma.sync.aligned.m16n8k16.row.col.f32.bf16.bf16.f32 "
        "{%0,%1,%2,%3}, {%4,%5,%6,%7}, {%8,%9}, {%0,%1,%2,%3};"
        : "+f"(c[0]), "+f"(c[1]), "+f"(c[2]), "+f"(c[3])
        : "r"(a[0]), "r"(a[1]), "r"(a[2]), "r"(a[3]), "r"(b[0]), "r"(b[1]));
}

// fast exp2 on FMA pipe (deg-5, rel err ~2e-6), x <= 0
__device__ __forceinline__ float fexp2(float x) {
    x = fmaxf(x, -126.0f);
    int ni = __float2int_rn(x);
    float f = x - (float)ni;
    float p = 1.33336498e-3f;
    p = fmaf(p, f, 9.61804464e-3f);
    p = fmaf(p, f, 5.55036498e-2f);
    p = fmaf(p, f, 2.40226507e-1f);
    p = fmaf(p, f, 6.93147182e-1f);
    p = fmaf(p, f, 1.0f);
    return p * __int_as_float((ni + 127) << 23);
}

__device__ __forceinline__ uint32_t pack_bf162(float x, float y) {
    __nv_bfloat162 h = __floats2bfloat162_rn(x, y);
    return *(uint32_t*)&h;
}
__device__ __forceinline__ void split2(float x, float y, uint32_t& hi, uint32_t& lo) {
    __nv_bfloat162 h = __floats2bfloat162_rn(x, y);
    float2 hf = __bfloat1622float2(h);
    __nv_bfloat162 l2 = __floats2bfloat162_rn(x - hf.x, y - hf.y);
    hi = *(uint32_t*)&h;
    lo = *(uint32_t*)&l2;
}

// ============================================================================
// bf16 hi/lo split conversion kernels (QKV GEMM inputs)
// ============================================================================
__global__ __launch_bounds__(256) void cvt_x_kernel(const float* __restrict__ x) {
    int i = (blockIdx.x * 256 + threadIdx.x) * 4;
    float4 v = *(const float4*)&x[i];
    float vv[4] = {v.x, v.y, v.z, v.w};
#pragma unroll
    for (int j = 0; j < 4; j++) {
        __nv_bfloat16 hi = __float2bfloat16_rn(vv[j]);
        __nv_bfloat16 lo = __float2bfloat16_rn(vv[j] - __bfloat162float(hi));
        g_xhi[i + j] = hi;
        g_xlo[i + j] = lo;
    }
}

__global__ __launch_bounds__(256) void cvt_w_kernel(
    const float* __restrict__ Wq, const float* __restrict__ Wk,
    const float* __restrict__ Wv) {
    int t = blockIdx.x * 256 + threadIdx.x;
    int part = t >> 20;
    int rem = t & 1048575;
    int h = rem >> 16;
    int k = (rem >> 6) & 1023;
    int e = rem & 63;
    const float* Wp = (part == 0) ? Wq : (part == 1) ? Wk : Wv;
    float v = Wp[h * (DIN * DH) + k * DH + e];
    __nv_bfloat16 hi = __float2bfloat16_rn(v);
    __nv_bfloat16 lo = __float2bfloat16_rn(v - __bfloat162float(hi));
    int n = part * 1024 + h * 64 + e;
    g_whi[(size_t)n * DIN + k] = hi;
    g_wlo[(size_t)n * DIN + k] = lo;
}

// ============================================================================
// QKV GEMM via mma.sync bf16 (3-pass split).
// Epilogue: Q -> pre-scaled split bf16; K -> split bf16; V -> fp32 (for vT).
// ============================================================================
#define BK      32
#define NCHUNK  (DIN / BK)
#define ROWB    80
#define A_HI    0
#define A_LO    10240
#define B_HI    20480
#define B_LO    30720
#define STAGE_B 40960

__global__ __launch_bounds__(256) void qkv_mma_kernel(
    const float* __restrict__ bq, const float* __restrict__ bk,
    const float* __restrict__ bv)
{
    extern __shared__ __align__(128) char smem[];
    const uint32_t sb0 = smem_u32(smem);
    const int tid = threadIdx.x;
    const int wid = tid >> 5, l = tid & 31;
    const int wm = wid & 1, wn = wid >> 1;
    const int bm = blockIdx.x;
    const int bn = blockIdx.y;

    const int arow0 = bm * 128, brow0 = bn * 128;

    uint32_t aoff[4], boff[2];
#pragma unroll
    for (int mi = 0; mi < 4; mi++) {
        int row = wm * 64 + mi * 16 + (l & 15);
        int col = ((l >> 4) & 1) * 8;
        aoff[mi] = (uint32_t)(row * ROWB + col * 2);
    }
#pragma unroll
    for (int bg = 0; bg < 2; bg++) {
        int nrow = wn * 32 + bg * 16 + ((l >> 4) & 1) * 8 + (l & 7);
        int col = ((l >> 3) & 1) * 8;
        boff[bg] = (uint32_t)(nrow * ROWB + col * 2);
    }

    float acc[4][4][4];
#pragma unroll
    for (int i = 0; i < 4; i++)
#pragma unroll
        for (int j = 0; j < 4; j++)
#pragma unroll
            for (int q = 0; q < 4; q++) acc[i][j][q] = 0.0f;

    auto load_chunk = [&](int c, int s) {
        uint32_t base = sb0 + (uint32_t)s * STAGE_B;
#pragma unroll
        for (int i = 0; i < 2; i++) {
            int slot = tid + i * 256;
            int row = slot >> 2, kg = slot & 3;
            uint32_t so = (uint32_t)(row * ROWB + kg * 16);
            size_t goA = (size_t)(arow0 + row) * DIN + c * BK + kg * 8;
            size_t goB = (size_t)(brow0 + row) * DIN + c * BK + kg * 8;
            cp16(base + A_HI + so, g_xhi + goA);
            cp16(base + A_LO + so, g_xlo + goA);
            cp16(base + B_HI + so, g_whi + goB);
            cp16(base + B_LO + so, g_wlo + goB);
        }
    };

    load_chunk(0, 0);
    CP_COMMIT();
    load_chunk(1, 1);
    CP_COMMIT();

    for (int c = 0; c < NCHUNK; c++) {
        int s = c & 1;
        if (c >= NCHUNK - 2) { CP_WAIT(0); } else { CP_WAIT(1); }
        __syncthreads();

        uint32_t base = sb0 + (uint32_t)s * STAGE_B;
#pragma unroll
        for (int ks = 0; ks < 2; ks++) {
            uint32_t kadd = (uint32_t)(ks * 32);
            uint32_t ahi[4][4], alo[4][4], bhi[4][2], blo[4][2];
#pragma unroll
            for (int mi = 0; mi < 4; mi++) {
                ldsm_x4(ahi[mi], base + A_HI + aoff[mi] + kadd);
                ldsm_x4(alo[mi], base + A_LO + aoff[mi] + kadd);
            }
#pragma unroll
            for (int bg = 0; bg < 2; bg++) {
                uint32_t r[4];
                ldsm_x4(r, base + B_HI + boff[bg] + kadd);
                bhi[bg * 2][0] = r[0]; bhi[bg * 2][1] = r[1];
                bhi[bg * 2 + 1][0] = r[2]; bhi[bg * 2 + 1][1] = r[3];
                ldsm_x4(r, base + B_LO + boff[bg] + kadd);
                blo[bg * 2][0] = r[0]; blo[bg * 2][1] = r[1];
                blo[bg * 2 + 1][0] = r[2]; blo[bg * 2 + 1][1] = r[3];
            }
#pragma unroll
            for (int mi = 0; mi < 4; mi++)
#pragma unroll
                for (int ni = 0; ni < 4; ni++) {
                    mma_bf16(acc[mi][ni], ahi[mi], bhi[ni]);
                    mma_bf16(acc[mi][ni], ahi[mi], blo[ni]);
                    mma_bf16(acc[mi][ni], alo[mi], bhi[ni]);
                }
        }

        __syncthreads();
        if (c + 2 < NCHUNK) {
            load_chunk(c + 2, s);
            CP_COMMIT();
        }
    }

    const int part = bn >> 3;
    const float* __restrict__ bp = (part == 0) ? bq : (part == 1) ? bk : bv;
    const int npart0 = (bn & 7) * 128 + wn * 32;
    const float scl = (part == 0) ? SCALE_LOG2E : 1.0f;
    __nv_bfloat16* __restrict__ ohi = (part == 0) ? a_qhi : a_khi;
    __nv_bfloat16* __restrict__ olo = (part == 0) ? a_qlo : a_klo;

#pragma unroll
    for (int mi = 0; mi < 4; mi++) {
        int m0 = arow0 + wm * 64 + mi * 16 + (l >> 2);
#pragma unroll
        for (int ni = 0; ni < 4; ni++) {
            int ncol = npart0 + ni * 8 + 2 * (l & 3);
            int h = ncol >> 6, e = ncol & 63;
            float b0 = bp[h * DH + e], b1 = bp[h * DH + e + 1];
#pragma unroll
            for (int half = 0; half < 2; half++) {
                int m = m0 + half * 8;
                int bb = m >> 11, sIdx = m & 2047;
                float v0 = acc[mi][ni][half * 2 + 0] + b0;
                float v1 = acc[mi][ni][half * 2 + 1] + b1;
                size_t idx = (((size_t)bb * H_ + h) * S_ + sIdx) * DH + e;
                if (part < 2) {
                    uint32_t hi, lo;
                    split2(v0 * scl, v1 * scl, hi, lo);
                    *(uint32_t*)&ohi[idx] = hi;
                    *(uint32_t*)&olo[idx] = lo;
                } else {
                    float2 v; v.x = v0; v.y = v1;
                    *(float2*)&g_v[idx] = v;
                }
            }
        }
    }
}

// ============================================================================
// V transpose + split: g_v [bh][s][e] -> a_vthi/a_vtlo [bh][e][s]
// ============================================================================
__global__ __launch_bounds__(256) void vt_kernel() {
    __shared__ float t[32][65];
    const int tid = threadIdx.x;
    const int bh = blockIdx.y;
    const int s0 = blockIdx.x * 32;
    const float* __restrict__ vp = g_v + (size_t)bh * S_ * DH;
#pragma unroll
    for (int i = 0; i < 8; i++) {
        int idx = tid + i * 256;
        int r = idx >> 6, e = idx & 63;
        t[r][e] = vp[(size_t)(s0 + r) * DH + e];
    }
    __syncthreads();
    size_t ob = (size_t)bh * DH * S_;
#pragma unroll
    for (int i = 0; i < 8; i++) {
        int idx = tid + i * 256;
        int e = idx >> 5, sc = idx & 31;
        float v = t[sc][e];
        __nv_bfloat16 hi = __float2bfloat16_rn(v);
        a_vthi[ob + (size_t)e * S_ + s0 + sc] = hi;
        a_vtlo[ob + (size_t)e * S_ + s0 + sc] =
            __float2bfloat16_rn(v - __bfloat162float(hi));
    }
}

// ============================================================================
// Causal flash attention on mma.sync bf16 (3-pass splits), poly exp2.
// Block: 256 thr (8 warps), q-tile 128 rows; key tile 64.
// smem rows padded to 144B (64 bf16 + 16B) -> conflict-free ldmatrix.
// ============================================================================
#define ARB   144                  // bytes per padded 64-elem bf16 row
#define QHI_O 0
#define QLO_O 18432
#define STG_O 36864                // stage base; stage size 36864
#define KHI_O 0
#define KLO_O 9216
#define VHI_O 18432
#define VLO_O 27648
#define ATT_SMEM (36864 + 2 * 36864)

__global__ __launch_bounds__(256, 1) void attn_mma_kernel()
{
    extern __shared__ __align__(128) char smem[];
    const uint32_t sb = smem_u32(smem);
    const int tid = threadIdx.x;
    const int w = tid >> 5, l = tid & 31;
    const int qt = blockIdx.x;        // 0..15
    const int bh = blockIdx.y;        // 0..63

    const __nv_bfloat16* __restrict__ qhi = a_qhi + (size_t)bh * S_ * DH;
    const __nv_bfloat16* __restrict__ qlo = a_qlo + (size_t)bh * S_ * DH;
    const __nv_bfloat16* __restrict__ khi = a_khi + (size_t)bh * S_ * DH;
    const __nv_bfloat16* __restrict__ klo = a_klo + (size_t)bh * S_ * DH;
    const __nv_bfloat16* __restrict__ vth = a_vthi + (size_t)bh * DH * S_;
    const __nv_bfloat16* __restrict__ vtl = a_vtlo + (size_t)bh * DH * S_;

    // ---- load Q tile (128x64, hi+lo) ----
#pragma unroll
    for (int i = 0; i < 4; i++) {
        int idx = tid + i * 256;             // 0..1023
        int row = idx >> 3, kg = idx & 7;
        uint32_t so = (uint32_t)(row * ARB + kg * 16);
        size_t go = (size_t)(qt * 128 + row) * DH + kg * 8;
        cp16(sb + QHI_O + so, qhi + go);
        cp16(sb + QLO_O + so, qlo + go);
    }

    auto load_kv = [&](int kt, int s) {
        uint32_t base = sb + STG_O + (uint32_t)s * 36864;
#pragma unroll
        for (int i = 0; i < 2; i++) {
            int idx = tid + i * 256;         // 0..511
            int row = idx >> 3, kg = idx & 7;
            uint32_t so = (uint32_t)(row * ARB + kg * 16);
            size_t gk = (size_t)(kt * 64 + row) * DH + kg * 8;
            size_t gv = (size_t)row * S_ + kt * 64 + kg * 8;
            cp16(base + KHI_O + so, khi + gk);
            cp16(base + KLO_O + so, klo + gk);
            cp16(base + VHI_O + so, vth + gv);
            cp16(base + VLO_O + so, vtl + gv);
        }
    };

    const int nkt = 2 * qt + 2;
    load_kv(0, 0);
    CP_COMMIT();

    float o[8][4];
#pragma unroll
    for (int i = 0; i < 8; i++)
#pragma unroll
        for (int j = 0; j < 4; j++) o[i][j] = 0.0f;
    float m0 = -1e30f, m1 = -1e30f, l0 = 0.0f, l1 = 0.0f;

    const int grow0 = qt * 128 + w * 16 + (l >> 2);
    const int grow1 = grow0 + 8;
    const uint32_t qa0 = sb + QHI_O + (uint32_t)((w * 16 + (l & 15)) * ARB
                                                 + ((l >> 4) & 1) * 16);
    const uint32_t bsel = (uint32_t)((8 * ((l >> 4) & 1) + (l & 7)) * ARB
                                     + ((l >> 3) & 1) * 16);

    for (int kt = 0; kt < nkt; kt++) {
        int s = kt & 1;
        CP_WAIT(0);
        __syncthreads();
        if (kt + 1 < nkt) {
            load_kv(kt + 1, 1 - s);
            CP_COMMIT();
        }
        uint32_t base = sb + STG_O + (uint32_t)s * 36864;

        // ---- S = Q K^T (3-pass split) ----
        float sc[8][4];
#pragma unroll
        for (int i = 0; i < 8; i++)
#pragma unroll
            for (int j = 0; j < 4; j++) sc[i][j] = 0.0f;

#pragma unroll
        for (int ks = 0; ks < 4; ks++) {
            uint32_t ahr[4], alr[4];
            ldsm_x4(ahr, qa0 + ks * 32);
            ldsm_x4(alr, qa0 + QLO_O + ks * 32);
#pragma unroll
            for (int nfp = 0; nfp < 4; nfp++) {
                uint32_t badd = base + KHI_O + bsel + (uint32_t)(nfp * 16 * ARB + ks * 32);
                uint32_t bh4[4], bl4[4];
                ldsm_x4(bh4, badd);
                ldsm_x4(bl4, badd + KLO_O);
                mma_bf16(sc[2 * nfp],     ahr, bh4);
                mma_bf16(sc[2 * nfp],     ahr, bl4);
                mma_bf16(sc[2 * nfp],     alr, bh4);
                mma_bf16(sc[2 * nfp + 1], ahr, bh4 + 2);
                mma_bf16(sc[2 * nfp + 1], ahr, bl4 + 2);
                mma_bf16(sc[2 * nfp + 1], alr, bh4 + 2);
            }
        }

        // ---- causal mask on diagonal tiles ----
        if (kt >= 2 * qt) {
#pragma unroll
            for (int nf = 0; nf < 8; nf++) {
                int gc = kt * 64 + nf * 8 + 2 * (l & 3);
                if (gc     > grow0) sc[nf][0] = -1e30f;
                if (gc + 1 > grow0) sc[nf][1] = -1e30f;
                if (gc     > grow1) sc[nf][2] = -1e30f;
                if (gc + 1 > grow1) sc[nf][3] = -1e30f;
            }
        }

        // ---- online softmax (log2 domain; Q pre-scaled) ----
        float mx0 = -1e30f, mx1 = -1e30f;
#pragma unroll
        for (int nf = 0; nf < 8; nf++) {
            mx0 = fmaxf(mx0, fmaxf(sc[nf][0], sc[nf][1]));
            mx1 = fmaxf(mx1, fmaxf(sc[nf][2], sc[nf][3]));
        }
#pragma unroll
        for (int off = 1; off < 4; off <<= 1) {
            mx0 = fmaxf(mx0, __shfl_xor_sync(0xffffffffu, mx0, off));
            mx1 = fmaxf(mx1, __shfl_xor_sync(0xffffffffu, mx1, off));
        }
        float mn0 = fmaxf(m0, mx0), mn1 = fmaxf(m1, mx1);
        float al0 = fexp2(m0 - mn0), al1 = fexp2(m1 - mn1);
        m0 = mn0; m1 = mn1;

        float rs0 = 0.0f, rs1 = 0.0f;
#pragma unroll
        for (int nf = 0; nf < 8; nf++) {
            sc[nf][0] = fexp2(sc[nf][0] - mn0);
            sc[nf][1] = fexp2(sc[nf][1] - mn0);
            sc[nf][2] = fexp2(sc[nf][2] - mn1);
            sc[nf][3] = fexp2(sc[nf][3] - mn1);
            rs0 += sc[nf][0] + sc[nf][1];
            rs1 += sc[nf][2] + sc[nf][3];
        }
#pragma unroll
        for (int off = 1; off < 4; off <<= 1) {
            rs0 += __shfl_xor_sync(0xffffffffu, rs0, off);
            rs1 += __shfl_xor_sync(0xffffffffu, rs1, off);
        }
        l0 = l0 * al0 + rs0;
        l1 = l1 * al1 + rs1;
#pragma unroll
        for (int nf = 0; nf < 8; nf++) {
            o[nf][0] *= al0; o[nf][1] *= al0;
            o[nf][2] *= al1; o[nf][3] *= al1;
        }

        // ---- pack P fragments (hi/lo) ----
        uint32_t ph[4][4], pl[4][4];
#pragma unroll
        for (int ks = 0; ks < 4; ks++) {
            split2(sc[2 * ks][0],     sc[2 * ks][1],     ph[ks][0], pl[ks][0]);
            split2(sc[2 * ks][2],     sc[2 * ks][3],     ph[ks][1], pl[ks][1]);
            split2(sc[2 * ks + 1][0], sc[2 * ks + 1][1], ph[ks][2], pl[ks][2]);
            split2(sc[2 * ks + 1][2], sc[2 * ks + 1][3], ph[ks][3], pl[ks][3]);
        }

        // ---- O += P V (3-pass split) ----
#pragma unroll
        for (int ks = 0; ks < 4; ks++) {
#pragma unroll
            for (int np = 0; np < 4; np++) {
                uint32_t vadd = base + VHI_O + bsel + (uint32_t)(np * 16 * ARB + ks * 32);
                uint32_t vh4[4], vl4[4];
                ldsm_x4(vh4, vadd);
                ldsm_x4(vl4, vadd + 9216);
                mma_bf16(o[2 * np],     ph[ks], vh4);
                mma_bf16(o[2 * np],     pl[ks], vh4);
                mma_bf16(o[2 * np],     ph[ks], vl4);
                mma_bf16(o[2 * np + 1], ph[ks], vh4 + 2);
                mma_bf16(o[2 * np + 1], pl[ks], vh4 + 2);
                mma_bf16(o[2 * np + 1], ph[ks], vl4 + 2);
            }
        }
    }

    // ---- write O / l ----
    const int b = bh >> 4, h = bh & 15;
    float inv0 = 1.0f / l0, inv1 = 1.0f / l1;
    size_t r0 = (size_t)(b * S_ + grow0) * (H_ * DH) + h * DH;
    size_t r1 = (size_t)(b * S_ + grow1) * (H_ * DH) + h * DH;
#pragma unroll
    for (int nf = 0; nf < 8; nf++) {
        int e = nf * 8 + 2 * (l & 3);
        float2 v0; v0.x = o[nf][0] * inv0; v0.y = o[nf][1] * inv0;
        float2 v1; v1.x = o[nf][2] * inv1; v1.y = o[nf][3] * inv1;
        *(float2*)&g_att[r0 + e] = v0;
        *(float2*)&g_att[r1 + e] = v1;
    }
}

// ============================================================================
// Kernel: output projection (unchanged)
// ============================================================================
__global__ __launch_bounds__(256) void oproj_kernel(
    const float* __restrict__ Wo, const float* __restrict__ bo,
    float* __restrict__ out)
{
    __shared__ float Ats[16][68];
    __shared__ float Ws2[16][64];

    const int m0 = blockIdx.x * 64;
    const int tid = threadIdx.x;
    const int tx = tid & 15, ty = tid >> 4;
    const int ty4 = ty * 4, tx4 = tx * 4;

    float acc[4][4];
#pragma unroll
    for (int i = 0; i < 4; i++)
#pragma unroll
        for (int j = 0; j < 4; j++) acc[i][j] = 0.0f;

    for (int k0 = 0; k0 < DIN; k0 += 16) {
        __syncthreads();
        for (int i = tid; i < 64 * 16; i += 256) {
            int r = i >> 4, kc = i & 15;
            Ats[kc][r] = g_att[(size_t)(m0 + r) * DIN + k0 + kc];
        }
        for (int i = tid; i < 16 * 64; i += 256) {
            int kk = i >> 6, n = i & 63;
            Ws2[kk][n] = Wo[(k0 + kk) * DH + n];
        }
        __syncthreads();

#pragma unroll
        for (int kk = 0; kk < 16; kk++) {
            float4 a = *(const float4*)&Ats[kk][ty4];
            float4 w = *(const float4*)&Ws2[kk][tx4];
            float av[4] = {a.x, a.y, a.z, a.w};
            float wv[4] = {w.x, w.y, w.z, w.w};
#pragma unroll
            for (int i = 0; i < 4; i++)
#pragma unroll
                for (int j = 0; j < 4; j++) acc[i][j] += av[i] * wv[j];
        }
    }

#pragma unroll
    for (int i = 0; i < 4; i++)
#pragma unroll
        for (int j = 0; j < 4; j++)
            out[(size_t)(m0 + ty4 + i) * DH + tx4 + j] = acc[i][j] + bo[tx4 + j];
}

// ============================================================================
extern "C" void kernel_launch(void* const* d_in, const int* in_sizes, int n_in,
                              void* d_out, int out_size)
{
    const float* x  = (const float*)d_in[0];
    const float* Wq = (const float*)d_in[1];
    const float* bq = (const float*)d_in[2];
    const float* Wk = (const float*)d_in[3];
    const float* bk = (const float*)d_in[4];
    const float* Wv = (const float*)d_in[5];
    const float* bv = (const float*)d_in[6];
    const float* Wo = (const float*)d_in[7];
    const float* bo = (const float*)d_in[8];
    float* out = (float*)d_out;

    cudaFuncSetAttribute(qkv_mma_kernel, cudaFuncAttributeMaxDynamicSharedMemorySize,
                         2 * STAGE_B);
    cudaFuncSetAttribute(attn_mma_kernel, cudaFuncAttributeMaxDynamicSharedMemorySize,
                         ATT_SMEM);

    cvt_x_kernel<<<8192, 256>>>(x);
    cvt_w_kernel<<<12288, 256>>>(Wq, Wk, Wv);
    qkv_mma_kernel<<<dim3(64, 24), 256, 2 * STAGE_B>>>(bq, bk, bv);
    vt_kernel<<<dim3(64, 64), 256>>>();
    attn_mma_kernel<<<dim3(16, 64), 256, ATT_SMEM>>>();
    oproj_kernel<<<M_ / 64, 256>>>(Wo, bo, out);
}

// round 5
// speedup vs baseline: 3.1926x; 1.4058x over previous
#include <cuda_runtime.h>
#include <cuda_fp16.h>
#include <math.h>
#include <stdint.h>

#define B_   4
#define S_   2048
#define DIN  1024
#define H_   16
#define DH   64
#define M_   (B_ * S_)       // 8192
#define NTOT 3072
#define BH_  (B_ * H_)       // 64

// ---- scratch (device globals: allocation-free) ----
__device__ float g_v[BH_ * S_ * DH];       // fp32 V (input to transpose)
__device__ float g_att[M_ * H_ * DH];      // [B*S, H*DH]

// fp16 attention operands
__device__ __half a_qhi[BH_ * S_ * DH];    // [bh][s][e], unscaled
__device__ __half a_qlo[BH_ * S_ * DH];
__device__ __half a_khi[BH_ * S_ * DH];    // single fp16
__device__ __half a_vthi[BH_ * DH * S_];   // [bh][e][s]
__device__ __half a_vtlo[BH_ * DH * S_];

// fp16 operands for QKV GEMM (X split, W single)
__device__ __half g_xhi[M_ * DIN];
__device__ __half g_xlo[M_ * DIN];
__device__ __half g_whi[NTOT * DIN];

#define SCALE_LOG2E 0.18033688011112042591999058f  // 0.125 * log2(e)

// ============================================================================
// helpers
// ============================================================================
__device__ __forceinline__ uint32_t smem_u32(const void* p) {
    uint32_t a;
    asm("{ .reg .u64 t; cvta.to.shared.u64 t, %1; cvt.u32.u64 %0, t; }"
        : "=r"(a) : "l"(p));
    return a;
}
__device__ __forceinline__ void cp16(uint32_t dst, const void* src) {
    asm volatile("cp.async.cg.shared.global [%0], [%1], 16;" :: "r"(dst), "l"(src));
}
#define CP_COMMIT() asm volatile("cp.async.commit_group;" ::: "memory")
#define CP_WAIT(n)  asm volatile("cp.async.wait_group %0;" :: "n"(n) : "memory")

__device__ __forceinline__ void ldsm_x4(uint32_t* r, uint32_t addr) {
    asm volatile("ldmatrix.sync.aligned.m8n8.x4.shared.b16 {%0,%1,%2,%3}, [%4];"
                 : "=r"(r[0]), "=r"(r[1]), "=r"(r[2]), "=r"(r[3]) : "r"(addr));
}
__device__ __forceinline__ void mma_f16(float* c, const uint32_t* a, const uint32_t* b) {
    asm volatile(
        "mma.sync.aligned.m16n8k16.row.col.f32.f16.f16.f32 "
        "{%0,%1,%2,%3}, {%4,%5,%6,%7}, {%8,%9}, {%0,%1,%2,%3};"
        : "+f"(c[0]), "+f"(c[1]), "+f"(c[2]), "+f"(c[3])
        : "r"(a[0]), "r"(a[1]), "r"(a[2]), "r"(a[3]), "r"(b[0]), "r"(b[1]));
}

// fast exp2 on FMA pipe (deg-5, rel err ~2e-6)
__device__ __forceinline__ float fexp2(float x) {
    x = fmaxf(x, -126.0f);
    int ni = __float2int_rn(x);
    float f = x - (float)ni;
    float p = 1.33336498e-3f;
    p = fmaf(p, f, 9.61804464e-3f);
    p = fmaf(p, f, 5.55036498e-2f);
    p = fmaf(p, f, 2.40226507e-1f);
    p = fmaf(p, f, 6.93147182e-1f);
    p = fmaf(p, f, 1.0f);
    return p * __int_as_float((ni + 127) << 23);
}

__device__ __forceinline__ uint32_t pack_h2(float x, float y) {
    __half2 h = __floats2half2_rn(x, y);
    return *(uint32_t*)&h;
}
__device__ __forceinline__ void split2h(float x, float y, uint32_t& hi, uint32_t& lo) {
    __half2 h = __floats2half2_rn(x, y);
    float2 hf = __half22float2(h);
    __half2 l2 = __floats2half2_rn(x - hf.x, y - hf.y);
    hi = *(uint32_t*)&h;
    lo = *(uint32_t*)&l2;
}

// ============================================================================
// conversion kernels (QKV GEMM inputs)
// ============================================================================
__global__ __launch_bounds__(256) void cvt_x_kernel(const float* __restrict__ x) {
    int i = (blockIdx.x * 256 + threadIdx.x) * 4;
    float4 v = *(const float4*)&x[i];
    float vv[4] = {v.x, v.y, v.z, v.w};
#pragma unroll
    for (int j = 0; j < 4; j += 2) {
        uint32_t hi, lo;
        split2h(vv[j], vv[j + 1], hi, lo);
        *(uint32_t*)&g_xhi[i + j] = hi;
        *(uint32_t*)&g_xlo[i + j] = lo;
    }
}

__global__ __launch_bounds__(256) void cvt_w_kernel(
    const float* __restrict__ Wq, const float* __restrict__ Wk,
    const float* __restrict__ Wv) {
    int t = blockIdx.x * 256 + threadIdx.x;
    int part = t >> 20;
    int rem = t & 1048575;
    int h = rem >> 16;
    int k = (rem >> 6) & 1023;
    int e = rem & 63;
    const float* Wp = (part == 0) ? Wq : (part == 1) ? Wk : Wv;
    float v = Wp[h * (DIN * DH) + k * DH + e];
    int n = part * 1024 + h * 64 + e;
    g_whi[(size_t)n * DIN + k] = __float2half_rn(v);
}

// ============================================================================
// QKV GEMM via mma.sync fp16, 2-pass A-side split.
// 128x128 tile, BK=32, 3-stage cp.async pipeline, 1 barrier/iter.
// ============================================================================
#define BK      32
#define NCHUNK  (DIN / BK)
#define ROWB    80
#define A_HI    0
#define A_LO    10240
#define B_W     20480
#define STAGE_B 30720

__global__ __launch_bounds__(256) void qkv_mma_kernel(
    const float* __restrict__ bq, const float* __restrict__ bk,
    const float* __restrict__ bv)
{
    extern __shared__ __align__(128) char smem[];
    const uint32_t sb0 = smem_u32(smem);
    const int tid = threadIdx.x;
    const int wid = tid >> 5, l = tid & 31;
    const int wm = wid & 1, wn = wid >> 1;
    const int bm = blockIdx.x;
    const int bn = blockIdx.y;

    const int arow0 = bm * 128, brow0 = bn * 128;

    uint32_t aoff[4], boff[2];
#pragma unroll
    for (int mi = 0; mi < 4; mi++) {
        int row = wm * 64 + mi * 16 + (l & 15);
        int col = ((l >> 4) & 1) * 8;
        aoff[mi] = (uint32_t)(row * ROWB + col * 2);
    }
#pragma unroll
    for (int bg = 0; bg < 2; bg++) {
        int nrow = wn * 32 + bg * 16 + ((l >> 4) & 1) * 8 + (l & 7);
        int col = ((l >> 3) & 1) * 8;
        boff[bg] = (uint32_t)(nrow * ROWB + col * 2);
    }

    float acc[4][4][4];
#pragma unroll
    for (int i = 0; i < 4; i++)
#pragma unroll
        for (int j = 0; j < 4; j++)
#pragma unroll
            for (int q = 0; q < 4; q++) acc[i][j][q] = 0.0f;

    auto load_chunk = [&](int c, int s) {
        uint32_t base = sb0 + (uint32_t)s * STAGE_B;
#pragma unroll
        for (int i = 0; i < 2; i++) {
            int slot = tid + i * 256;
            int row = slot >> 2, kg = slot & 3;
            uint32_t so = (uint32_t)(row * ROWB + kg * 16);
            size_t goA = (size_t)(arow0 + row) * DIN + c * BK + kg * 8;
            size_t goB = (size_t)(brow0 + row) * DIN + c * BK + kg * 8;
            cp16(base + A_HI + so, g_xhi + goA);
            cp16(base + A_LO + so, g_xlo + goA);
            cp16(base + B_W  + so, g_whi + goB);
        }
    };

    load_chunk(0, 0);
    CP_COMMIT();
    load_chunk(1, 1);
    CP_COMMIT();

    for (int c = 0; c < NCHUNK; c++) {
        int s = c % 3;
        if (c == NCHUNK - 1) { CP_WAIT(0); } else { CP_WAIT(1); }
        __syncthreads();

        uint32_t base = sb0 + (uint32_t)s * STAGE_B;
#pragma unroll
        for (int ks = 0; ks < 2; ks++) {
            uint32_t kadd = (uint32_t)(ks * 32);
            uint32_t ah[4][4], al[4][4], bw[4][2];
#pragma unroll
            for (int mi = 0; mi < 4; mi++) {
                ldsm_x4(ah[mi], base + A_HI + aoff[mi] + kadd);
                ldsm_x4(al[mi], base + A_LO + aoff[mi] + kadd);
            }
#pragma unroll
            for (int bg = 0; bg < 2; bg++) {
                uint32_t r[4];
                ldsm_x4(r, base + B_W + boff[bg] + kadd);
                bw[bg * 2][0] = r[0]; bw[bg * 2][1] = r[1];
                bw[bg * 2 + 1][0] = r[2]; bw[bg * 2 + 1][1] = r[3];
            }
#pragma unroll
            for (int mi = 0; mi < 4; mi++)
#pragma unroll
                for (int ni = 0; ni < 4; ni++) {
                    mma_f16(acc[mi][ni], ah[mi], bw[ni]);
                    mma_f16(acc[mi][ni], al[mi], bw[ni]);
                }
        }

        if (c + 2 < NCHUNK) {
            load_chunk(c + 2, (c + 2) % 3);
            CP_COMMIT();
        }
    }

    const int part = bn >> 3;
    const float* __restrict__ bp = (part == 0) ? bq : (part == 1) ? bk : bv;
    const int npart0 = (bn & 7) * 128 + wn * 32;

#pragma unroll
    for (int mi = 0; mi < 4; mi++) {
        int m0 = arow0 + wm * 64 + mi * 16 + (l >> 2);
#pragma unroll
        for (int ni = 0; ni < 4; ni++) {
            int ncol = npart0 + ni * 8 + 2 * (l & 3);
            int h = ncol >> 6, e = ncol & 63;
            float b0 = bp[h * DH + e], b1 = bp[h * DH + e + 1];
#pragma unroll
            for (int half = 0; half < 2; half++) {
                int m = m0 + half * 8;
                int bb = m >> 11, sIdx = m & 2047;
                float v0 = acc[mi][ni][half * 2 + 0] + b0;
                float v1 = acc[mi][ni][half * 2 + 1] + b1;
                size_t idx = (((size_t)bb * H_ + h) * S_ + sIdx) * DH + e;
                if (part == 0) {
                    uint32_t hi, lo;
                    split2h(v0, v1, hi, lo);
                    *(uint32_t*)&a_qhi[idx] = hi;
                    *(uint32_t*)&a_qlo[idx] = lo;
                } else if (part == 1) {
                    *(uint32_t*)&a_khi[idx] = pack_h2(v0, v1);
                } else {
                    float2 v; v.x = v0; v.y = v1;
                    *(float2*)&g_v[idx] = v;
                }
            }
        }
    }
}

// ============================================================================
// V transpose + split: g_v [bh][s][e] -> a_vthi/a_vtlo [bh][e][s]
// ============================================================================
__global__ __launch_bounds__(256) void vt_kernel() {
    __shared__ float t[32][65];
    const int tid = threadIdx.x;
    const int bh = blockIdx.y;
    const int s0 = blockIdx.x * 32;
    const float* __restrict__ vp = g_v + (size_t)bh * S_ * DH;
#pragma unroll
    for (int i = 0; i < 8; i++) {
        int idx = tid + i * 256;
        int r = idx >> 6, e = idx & 63;
        t[r][e] = vp[(size_t)(s0 + r) * DH + e];
    }
    __syncthreads();
    size_t ob = (size_t)bh * DH * S_;
#pragma unroll
    for (int i = 0; i < 8; i++) {
        int idx = tid + i * 256;
        int e = idx >> 5, sc = idx & 31;
        float v = t[sc][e];
        __half hi = __float2half_rn(v);
        a_vthi[ob + (size_t)e * S_ + s0 + sc] = hi;
        a_vtlo[ob + (size_t)e * S_ + s0 + sc] =
            __float2half_rn(v - __half2float(hi));
    }
}

// ============================================================================
// Causal flash attention, fp16 mma: QK 2-pass (Q split), PV 2-pass (V split).
// ============================================================================
#define ARB   144
#define QHI_O 0
#define QLO_O 18432
#define STG_O 36864          // stage size 27648: K | Vhi | Vlo
#define KHI_O 0
#define VHI_O 9216
#define VLO_O 18432
#define ATT_SMEM (36864 + 2 * 27648)

__global__ __launch_bounds__(256, 1) void attn_mma_kernel()
{
    extern __shared__ __align__(128) char smem[];
    const uint32_t sb = smem_u32(smem);
    const int tid = threadIdx.x;
    const int w = tid >> 5, l = tid & 31;
    const int qt = blockIdx.x;        // 0..15
    const int bh = blockIdx.y;        // 0..63

    const __half* __restrict__ qhi = a_qhi + (size_t)bh * S_ * DH;
    const __half* __restrict__ qlo = a_qlo + (size_t)bh * S_ * DH;
    const __half* __restrict__ khi = a_khi + (size_t)bh * S_ * DH;
    const __half* __restrict__ vth = a_vthi + (size_t)bh * DH * S_;
    const __half* __restrict__ vtl = a_vtlo + (size_t)bh * DH * S_;

    // ---- load Q tile (128x64, hi+lo) ----
#pragma unroll
    for (int i = 0; i < 4; i++) {
        int idx = tid + i * 256;
        int row = idx >> 3, kg = idx & 7;
        uint32_t so = (uint32_t)(row * ARB + kg * 16);
        size_t go = (size_t)(qt * 128 + row) * DH + kg * 8;
        cp16(sb + QHI_O + so, qhi + go);
        cp16(sb + QLO_O + so, qlo + go);
    }

    auto load_kv = [&](int kt, int s) {
        uint32_t base = sb + STG_O + (uint32_t)s * 27648;
#pragma unroll
        for (int i = 0; i < 2; i++) {
            int idx = tid + i * 256;
            int row = idx >> 3, kg = idx & 7;
            uint32_t so = (uint32_t)(row * ARB + kg * 16);
            size_t gk = (size_t)(kt * 64 + row) * DH + kg * 8;
            size_t gv = (size_t)row * S_ + kt * 64 + kg * 8;
            cp16(base + KHI_O + so, khi + gk);
            cp16(base + VHI_O + so, vth + gv);
            cp16(base + VLO_O + so, vtl + gv);
        }
    };

    const int nkt = 2 * qt + 2;
    load_kv(0, 0);
    CP_COMMIT();

    float o[8][4];
#pragma unroll
    for (int i = 0; i < 8; i++)
#pragma unroll
        for (int j = 0; j < 4; j++) o[i][j] = 0.0f;
    float m0 = -1e30f, m1 = -1e30f, l0 = 0.0f, l1 = 0.0f;

    const int grow0 = qt * 128 + w * 16 + (l >> 2);
    const int grow1 = grow0 + 8;
    const uint32_t qa0 = sb + QHI_O + (uint32_t)((w * 16 + (l & 15)) * ARB
                                                 + ((l >> 4) & 1) * 16);
    const uint32_t bsel = (uint32_t)((8 * ((l >> 4) & 1) + (l & 7)) * ARB
                                     + ((l >> 3) & 1) * 16);

    for (int kt = 0; kt < nkt; kt++) {
        int s = kt & 1;
        CP_WAIT(0);
        __syncthreads();
        if (kt + 1 < nkt) {
            load_kv(kt + 1, 1 - s);
            CP_COMMIT();
        }
        uint32_t base = sb + STG_O + (uint32_t)s * 27648;

        // ---- S = Q K^T (Q hi/lo 2-pass, K single) ----
        float sc[8][4];
#pragma unroll
        for (int i = 0; i < 8; i++)
#pragma unroll
            for (int j = 0; j < 4; j++) sc[i][j] = 0.0f;

#pragma unroll
        for (int ks = 0; ks < 4; ks++) {
            uint32_t ahr[4], alr[4];
            ldsm_x4(ahr, qa0 + ks * 32);
            ldsm_x4(alr, qa0 + QLO_O + ks * 32);
#pragma unroll
            for (int nfp = 0; nfp < 4; nfp++) {
                uint32_t kadd = base + KHI_O + bsel + (uint32_t)(nfp * 16 * ARB + ks * 32);
                uint32_t k4[4];
                ldsm_x4(k4, kadd);
                mma_f16(sc[2 * nfp],     ahr, k4);
                mma_f16(sc[2 * nfp],     alr, k4);
                mma_f16(sc[2 * nfp + 1], ahr, k4 + 2);
                mma_f16(sc[2 * nfp + 1], alr, k4 + 2);
            }
        }

        // ---- causal mask + scale into log2 domain ----
        if (kt >= 2 * qt) {
#pragma unroll
            for (int nf = 0; nf < 8; nf++) {
                int gc = kt * 64 + nf * 8 + 2 * (l & 3);
                if (gc     > grow0) sc[nf][0] = -1e30f;
                if (gc + 1 > grow0) sc[nf][1] = -1e30f;
                if (gc     > grow1) sc[nf][2] = -1e30f;
                if (gc + 1 > grow1) sc[nf][3] = -1e30f;
            }
        }
#pragma unroll
        for (int nf = 0; nf < 8; nf++) {
            sc[nf][0] *= SCALE_LOG2E; sc[nf][1] *= SCALE_LOG2E;
            sc[nf][2] *= SCALE_LOG2E; sc[nf][3] *= SCALE_LOG2E;
        }

        // ---- online softmax ----
        float mx0 = -1e30f, mx1 = -1e30f;
#pragma unroll
        for (int nf = 0; nf < 8; nf++) {
            mx0 = fmaxf(mx0, fmaxf(sc[nf][0], sc[nf][1]));
            mx1 = fmaxf(mx1, fmaxf(sc[nf][2], sc[nf][3]));
        }
#pragma unroll
        for (int off = 1; off < 4; off <<= 1) {
            mx0 = fmaxf(mx0, __shfl_xor_sync(0xffffffffu, mx0, off));
            mx1 = fmaxf(mx1, __shfl_xor_sync(0xffffffffu, mx1, off));
        }
        float mn0 = fmaxf(m0, mx0), mn1 = fmaxf(m1, mx1);
        float al0 = fexp2(m0 - mn0), al1 = fexp2(m1 - mn1);
        m0 = mn0; m1 = mn1;

        float rs0 = 0.0f, rs1 = 0.0f;
#pragma unroll
        for (int nf = 0; nf < 8; nf++) {
            sc[nf][0] = fexp2(sc[nf][0] - mn0);
            sc[nf][1] = fexp2(sc[nf][1] - mn0);
            sc[nf][2] = fexp2(sc[nf][2] - mn1);
            sc[nf][3] = fexp2(sc[nf][3] - mn1);
            rs0 += sc[nf][0] + sc[nf][1];
            rs1 += sc[nf][2] + sc[nf][3];
        }
#pragma unroll
        for (int off = 1; off < 4; off <<= 1) {
            rs0 += __shfl_xor_sync(0xffffffffu, rs0, off);
            rs1 += __shfl_xor_sync(0xffffffffu, rs1, off);
        }
        l0 = l0 * al0 + rs0;
        l1 = l1 * al1 + rs1;
#pragma unroll
        for (int nf = 0; nf < 8; nf++) {
            o[nf][0] *= al0; o[nf][1] *= al0;
            o[nf][2] *= al1; o[nf][3] *= al1;
        }

        // ---- pack P (single fp16) ----
        uint32_t ph[4][4];
#pragma unroll
        for (int ks = 0; ks < 4; ks++) {
            ph[ks][0] = pack_h2(sc[2 * ks][0],     sc[2 * ks][1]);
            ph[ks][1] = pack_h2(sc[2 * ks][2],     sc[2 * ks][3]);
            ph[ks][2] = pack_h2(sc[2 * ks + 1][0], sc[2 * ks + 1][1]);
            ph[ks][3] = pack_h2(sc[2 * ks + 1][2], sc[2 * ks + 1][3]);
        }

        // ---- O += P V (V hi/lo 2-pass) ----
#pragma unroll
        for (int ks = 0; ks < 4; ks++) {
#pragma unroll
            for (int np = 0; np < 4; np++) {
                uint32_t vadd = base + VHI_O + bsel + (uint32_t)(np * 16 * ARB + ks * 32);
                uint32_t vh4[4], vl4[4];
                ldsm_x4(vh4, vadd);
                ldsm_x4(vl4, vadd + (VLO_O - VHI_O));
                mma_f16(o[2 * np],     ph[ks], vh4);
                mma_f16(o[2 * np],     ph[ks], vl4);
                mma_f16(o[2 * np + 1], ph[ks], vh4 + 2);
                mma_f16(o[2 * np + 1], ph[ks], vl4 + 2);
            }
        }
    }

    // ---- write O ----
    const int b = bh >> 4, h = bh & 15;
    float inv0 = 1.0f / l0, inv1 = 1.0f / l1;
    size_t r0 = (size_t)(b * S_ + grow0) * (H_ * DH) + h * DH;
    size_t r1 = (size_t)(b * S_ + grow1) * (H_ * DH) + h * DH;
#pragma unroll
    for (int nf = 0; nf < 8; nf++) {
        int e = nf * 8 + 2 * (l & 3);
        float2 v0; v0.x = o[nf][0] * inv0; v0.y = o[nf][1] * inv0;
        float2 v1; v1.x = o[nf][2] * inv1; v1.y = o[nf][3] * inv1;
        *(float2*)&g_att[r0 + e] = v0;
        *(float2*)&g_att[r1 + e] = v1;
    }
}

// ============================================================================
// Kernel: output projection (fp32 FFMA)
// ============================================================================
__global__ __launch_bounds__(256) void oproj_kernel(
    const float* __restrict__ Wo, const float* __restrict__ bo,
    float* __restrict__ out)
{
    __shared__ float Ats[16][68];
    __shared__ float Ws2[16][64];

    const int m0 = blockIdx.x * 64;
    const int tid = threadIdx.x;
    const int tx = tid & 15, ty = tid >> 4;
    const int ty4 = ty * 4, tx4 = tx * 4;

    float acc[4][4];
#pragma unroll
    for (int i = 0; i < 4; i++)
#pragma unroll
        for (int j = 0; j < 4; j++) acc[i][j] = 0.0f;

    for (int k0 = 0; k0 < DIN; k0 += 16) {
        __syncthreads();
        for (int i = tid; i < 64 * 16; i += 256) {
            int r = i >> 4, kc = i & 15;
            Ats[kc][r] = g_att[(size_t)(m0 + r) * DIN + k0 + kc];
        }
        for (int i = tid; i < 16 * 64; i += 256) {
            int kk = i >> 6, n = i & 63;
            Ws2[kk][n] = Wo[(k0 + kk) * DH + n];
        }
        __syncthreads();

#pragma unroll
        for (int kk = 0; kk < 16; kk++) {
            float4 a = *(const float4*)&Ats[kk][ty4];
            float4 w = *(const float4*)&Ws2[kk][tx4];
            float av[4] = {a.x, a.y, a.z, a.w};
            float wv[4] = {w.x, w.y, w.z, w.w};
#pragma unroll
            for (int i = 0; i < 4; i++)
#pragma unroll
                for (int j = 0; j < 4; j++) acc[i][j] += av[i] * wv[j];
        }
    }

#pragma unroll
    for (int i = 0; i < 4; i++)
#pragma unroll
        for (int j = 0; j < 4; j++)
            out[(size_t)(m0 + ty4 + i) * DH + tx4 + j] = acc[i][j] + bo[tx4 + j];
}

// ============================================================================
extern "C" void kernel_launch(void* const* d_in, const int* in_sizes, int n_in,
                              void* d_out, int out_size)
{
    const float* x  = (const float*)d_in[0];
    const float* Wq = (const float*)d_in[1];
    const float* bq = (const float*)d_in[2];
    const float* Wk = (const float*)d_in[3];
    const float* bk = (const float*)d_in[4];
    const float* Wv = (const float*)d_in[5];
    const float* bv = (const float*)d_in[6];
    const float* Wo = (const float*)d_in[7];
    const float* bo = (const float*)d_in[8];
    float* out = (float*)d_out;

    cudaFuncSetAttribute(qkv_mma_kernel, cudaFuncAttributeMaxDynamicSharedMemorySize,
                         3 * STAGE_B);
    cudaFuncSetAttribute(attn_mma_kernel, cudaFuncAttributeMaxDynamicSharedMemorySize,
                         ATT_SMEM);

    cvt_x_kernel<<<8192, 256>>>(x);
    cvt_w_kernel<<<12288, 256>>>(Wq, Wk, Wv);
    qkv_mma_kernel<<<dim3(64, 24), 256, 3 * STAGE_B>>>(bq, bk, bv);
    vt_kernel<<<dim3(64, 64), 256>>>();
    attn_mma_kernel<<<dim3(16, 64), 256, ATT_SMEM>>>();
    oproj_kernel<<<M_ / 64, 256>>>(Wo, bo, out);
}

// round 6
// speedup vs baseline: 5.5321x; 1.7328x over previous
#include <cuda_runtime.h>
#include <cuda_fp16.h>
#include <math.h>
#include <stdint.h>

#define B_   4
#define S_   2048
#define DIN  1024
#define H_   16
#define DH   64
#define M_   (B_ * S_)       // 8192
#define NTOT 3072
#define BH_  (B_ * H_)       // 64

// ---- scratch (device globals: allocation-free) ----
__device__ float g_v[BH_ * S_ * DH];        // fp32 V (input to transpose)
__device__ __half g_atth[M_ * H_ * DH];     // fp16 attention output [B*S, H*DH]

// fp16 attention operands
__device__ __half a_qh[BH_ * S_ * DH];      // [bh][s][e], unscaled
__device__ __half a_kh[BH_ * S_ * DH];
__device__ __half a_vth[BH_ * DH * S_];     // [bh][e][s]

// fp16 operands for QKV GEMM / O-proj
__device__ __half g_xh[M_ * DIN];
__device__ __half g_wh[NTOT * DIN];         // [n][k]
__device__ __half g_woh[DH * DIN];          // [n][k] for O-proj (n=64)

#define SCALE_LOG2E 0.18033688011112042591999058f  // 0.125 * log2(e)

// ============================================================================
// helpers
// ============================================================================
__device__ __forceinline__ uint32_t smem_u32(const void* p) {
    uint32_t a;
    asm("{ .reg .u64 t; cvta.to.shared.u64 t, %1; cvt.u32.u64 %0, t; }"
        : "=r"(a) : "l"(p));
    return a;
}
__device__ __forceinline__ void cp16(uint32_t dst, const void* src) {
    asm volatile("cp.async.cg.shared.global [%0], [%1], 16;" :: "r"(dst), "l"(src));
}
#define CP_COMMIT() asm volatile("cp.async.commit_group;" ::: "memory")
#define CP_WAIT(n)  asm volatile("cp.async.wait_group %0;" :: "n"(n) : "memory")

__device__ __forceinline__ void ldsm_x4(uint32_t* r, uint32_t addr) {
    asm volatile("ldmatrix.sync.aligned.m8n8.x4.shared.b16 {%0,%1,%2,%3}, [%4];"
                 : "=r"(r[0]), "=r"(r[1]), "=r"(r[2]), "=r"(r[3]) : "r"(addr));
}
__device__ __forceinline__ void mma_f16(float* c, const uint32_t* a, const uint32_t* b) {
    asm volatile(
        "mma.sync.aligned.m16n8k16.row.col.f32.f16.f16.f32 "
        "{%0,%1,%2,%3}, {%4,%5,%6,%7}, {%8,%9}, {%0,%1,%2,%3};"
        : "+f"(c[0]), "+f"(c[1]), "+f"(c[2]), "+f"(c[3])
        : "r"(a[0]), "r"(a[1]), "r"(a[2]), "r"(a[3]), "r"(b[0]), "r"(b[1]));
}

// fast exp2 on FMA pipe (deg-5, rel err ~2e-6)
__device__ __forceinline__ float fexp2(float x) {
    x = fmaxf(x, -126.0f);
    int ni = __float2int_rn(x);
    float f = x - (float)ni;
    float p = 1.33336498e-3f;
    p = fmaf(p, f, 9.61804464e-3f);
    p = fmaf(p, f, 5.55036498e-2f);
    p = fmaf(p, f, 2.40226507e-1f);
    p = fmaf(p, f, 6.93147182e-1f);
    p = fmaf(p, f, 1.0f);
    return p * __int_as_float((ni + 127) << 23);
}

__device__ __forceinline__ uint32_t pack_h2(float x, float y) {
    __half2 h = __floats2half2_rn(x, y);
    return *(uint32_t*)&h;
}

// ============================================================================
// conversion kernels
// ============================================================================
__global__ __launch_bounds__(256) void cvt_x_kernel(const float* __restrict__ x) {
    int i = (blockIdx.x * 256 + threadIdx.x) * 4;
    float4 v = *(const float4*)&x[i];
    *(uint32_t*)&g_xh[i]     = pack_h2(v.x, v.y);
    *(uint32_t*)&g_xh[i + 2] = pack_h2(v.z, v.w);
}

__global__ __launch_bounds__(256) void cvt_w_kernel(
    const float* __restrict__ Wq, const float* __restrict__ Wk,
    const float* __restrict__ Wv, const float* __restrict__ Wo) {
    int t = blockIdx.x * 256 + threadIdx.x;
    if (t < 3145728) {
        int part = t >> 20;
        int rem = t & 1048575;
        int h = rem >> 16;
        int k = (rem >> 6) & 1023;
        int e = rem & 63;
        const float* Wp = (part == 0) ? Wq : (part == 1) ? Wk : Wv;
        float v = Wp[h * (DIN * DH) + k * DH + e];
        int n = part * 1024 + h * 64 + e;
        g_wh[(size_t)n * DIN + k] = __float2half_rn(v);
    } else {
        int r = t - 3145728;              // 0..65535 : Wo [1024][64]
        int k = r >> 6, n = r & 63;
        g_woh[(size_t)n * DIN + k] = __float2half_rn(Wo[k * DH + n]);
    }
}

// ============================================================================
// QKV GEMM, single-pass fp16 mma. 128x128 tile, BK=32, 3-stage pipeline.
// ============================================================================
#define BK      32
#define NCHUNK  (DIN / BK)
#define ROWB    80
#define B_W     10240
#define STAGE_B 20480

__global__ __launch_bounds__(256) void qkv_mma_kernel(
    const float* __restrict__ bq, const float* __restrict__ bk,
    const float* __restrict__ bv)
{
    extern __shared__ __align__(128) char smem[];
    const uint32_t sb0 = smem_u32(smem);
    const int tid = threadIdx.x;
    const int wid = tid >> 5, l = tid & 31;
    const int wm = wid & 1, wn = wid >> 1;
    const int bm = blockIdx.x;
    const int bn = blockIdx.y;

    const int arow0 = bm * 128, brow0 = bn * 128;

    uint32_t aoff[4], boff[2];
#pragma unroll
    for (int mi = 0; mi < 4; mi++) {
        int row = wm * 64 + mi * 16 + (l & 15);
        int col = ((l >> 4) & 1) * 8;
        aoff[mi] = (uint32_t)(row * ROWB + col * 2);
    }
#pragma unroll
    for (int bg = 0; bg < 2; bg++) {
        int nrow = wn * 32 + bg * 16 + ((l >> 4) & 1) * 8 + (l & 7);
        int col = ((l >> 3) & 1) * 8;
        boff[bg] = (uint32_t)(nrow * ROWB + col * 2);
    }

    float acc[4][4][4];
#pragma unroll
    for (int i = 0; i < 4; i++)
#pragma unroll
        for (int j = 0; j < 4; j++)
#pragma unroll
            for (int q = 0; q < 4; q++) acc[i][j][q] = 0.0f;

    auto load_chunk = [&](int c, int s) {
        uint32_t base = sb0 + (uint32_t)s * STAGE_B;
#pragma unroll
        for (int i = 0; i < 2; i++) {
            int slot = tid + i * 256;
            int row = slot >> 2, kg = slot & 3;
            uint32_t so = (uint32_t)(row * ROWB + kg * 16);
            cp16(base + so,       g_xh + (size_t)(arow0 + row) * DIN + c * BK + kg * 8);
            cp16(base + B_W + so, g_wh + (size_t)(brow0 + row) * DIN + c * BK + kg * 8);
        }
    };

    load_chunk(0, 0);
    CP_COMMIT();
    load_chunk(1, 1);
    CP_COMMIT();

    for (int c = 0; c < NCHUNK; c++) {
        int s = c % 3;
        if (c == NCHUNK - 1) { CP_WAIT(0); } else { CP_WAIT(1); }
        __syncthreads();

        uint32_t base = sb0 + (uint32_t)s * STAGE_B;
#pragma unroll
        for (int ks = 0; ks < 2; ks++) {
            uint32_t kadd = (uint32_t)(ks * 32);
            uint32_t ah[4][4], bw[4][2];
#pragma unroll
            for (int mi = 0; mi < 4; mi++)
                ldsm_x4(ah[mi], base + aoff[mi] + kadd);
#pragma unroll
            for (int bg = 0; bg < 2; bg++) {
                uint32_t r[4];
                ldsm_x4(r, base + B_W + boff[bg] + kadd);
                bw[bg * 2][0] = r[0]; bw[bg * 2][1] = r[1];
                bw[bg * 2 + 1][0] = r[2]; bw[bg * 2 + 1][1] = r[3];
            }
#pragma unroll
            for (int mi = 0; mi < 4; mi++)
#pragma unroll
                for (int ni = 0; ni < 4; ni++)
                    mma_f16(acc[mi][ni], ah[mi], bw[ni]);
        }

        if (c + 2 < NCHUNK) {
            load_chunk(c + 2, (c + 2) % 3);
            CP_COMMIT();
        }
    }

    const int part = bn >> 3;
    const float* __restrict__ bp = (part == 0) ? bq : (part == 1) ? bk : bv;
    const int npart0 = (bn & 7) * 128 + wn * 32;
    __half* __restrict__ oh = (part == 0) ? a_qh : a_kh;

#pragma unroll
    for (int mi = 0; mi < 4; mi++) {
        int m0 = arow0 + wm * 64 + mi * 16 + (l >> 2);
#pragma unroll
        for (int ni = 0; ni < 4; ni++) {
            int ncol = npart0 + ni * 8 + 2 * (l & 3);
            int h = ncol >> 6, e = ncol & 63;
            float b0 = bp[h * DH + e], b1 = bp[h * DH + e + 1];
#pragma unroll
            for (int half = 0; half < 2; half++) {
                int m = m0 + half * 8;
                int bb = m >> 11, sIdx = m & 2047;
                float v0 = acc[mi][ni][half * 2 + 0] + b0;
                float v1 = acc[mi][ni][half * 2 + 1] + b1;
                size_t idx = (((size_t)bb * H_ + h) * S_ + sIdx) * DH + e;
                if (part < 2) {
                    *(uint32_t*)&oh[idx] = pack_h2(v0, v1);
                } else {
                    float2 v; v.x = v0; v.y = v1;
                    *(float2*)&g_v[idx] = v;
                }
            }
        }
    }
}

// ============================================================================
// V transpose: g_v [bh][s][e] -> a_vth [bh][e][s] fp16
// ============================================================================
__global__ __launch_bounds__(256) void vt_kernel() {
    __shared__ float t[32][65];
    const int tid = threadIdx.x;
    const int bh = blockIdx.y;
    const int s0 = blockIdx.x * 32;
    const float* __restrict__ vp = g_v + (size_t)bh * S_ * DH;
#pragma unroll
    for (int i = 0; i < 8; i++) {
        int idx = tid + i * 256;
        int r = idx >> 6, e = idx & 63;
        t[r][e] = vp[(size_t)(s0 + r) * DH + e];
    }
    __syncthreads();
    size_t ob = (size_t)bh * DH * S_;
#pragma unroll
    for (int i = 0; i < 8; i++) {
        int idx = tid + i * 256;
        int e = idx >> 5, sc = idx & 31;
        a_vth[ob + (size_t)e * S_ + s0 + sc] = __float2half_rn(t[sc][e]);
    }
}

// ============================================================================
// Causal flash attention, single-pass fp16 mma throughout.
// ============================================================================
#define ARB    144
#define Q_O    0
#define STG_O  18432           // stage size 18432: K | V
#define V_O    9216
#define ATT_SMEM (18432 + 2 * 18432)

__global__ __launch_bounds__(256, 1) void attn_mma_kernel()
{
    extern __shared__ __align__(128) char smem[];
    const uint32_t sb = smem_u32(smem);
    const int tid = threadIdx.x;
    const int w = tid >> 5, l = tid & 31;
    const int qt = blockIdx.x;        // 0..15
    const int bh = blockIdx.y;        // 0..63

    const __half* __restrict__ qh = a_qh + (size_t)bh * S_ * DH;
    const __half* __restrict__ kh = a_kh + (size_t)bh * S_ * DH;
    const __half* __restrict__ vth = a_vth + (size_t)bh * DH * S_;

    // ---- load Q tile (128x64) ----
#pragma unroll
    for (int i = 0; i < 4; i++) {
        int idx = tid + i * 256;
        int row = idx >> 3, kg = idx & 7;
        uint32_t so = (uint32_t)(row * ARB + kg * 16);
        cp16(sb + Q_O + so, qh + (size_t)(qt * 128 + row) * DH + kg * 8);
    }

    auto load_kv = [&](int kt, int s) {
        uint32_t base = sb + STG_O + (uint32_t)s * 18432;
#pragma unroll
        for (int i = 0; i < 2; i++) {
            int idx = tid + i * 256;
            int row = idx >> 3, kg = idx & 7;
            uint32_t so = (uint32_t)(row * ARB + kg * 16);
            cp16(base + so,       kh + (size_t)(kt * 64 + row) * DH + kg * 8);
            cp16(base + V_O + so, vth + (size_t)row * S_ + kt * 64 + kg * 8);
        }
    };

    const int nkt = 2 * qt + 2;
    load_kv(0, 0);
    CP_COMMIT();

    float o[8][4];
#pragma unroll
    for (int i = 0; i < 8; i++)
#pragma unroll
        for (int j = 0; j < 4; j++) o[i][j] = 0.0f;
    float m0 = -1e30f, m1 = -1e30f, l0 = 0.0f, l1 = 0.0f;

    const int grow0 = qt * 128 + w * 16 + (l >> 2);
    const int grow1 = grow0 + 8;
    const uint32_t qa0 = sb + Q_O + (uint32_t)((w * 16 + (l & 15)) * ARB
                                               + ((l >> 4) & 1) * 16);
    const uint32_t bsel = (uint32_t)((8 * ((l >> 4) & 1) + (l & 7)) * ARB
                                     + ((l >> 3) & 1) * 16);

    for (int kt = 0; kt < nkt; kt++) {
        int s = kt & 1;
        CP_WAIT(0);
        __syncthreads();
        if (kt + 1 < nkt) {
            load_kv(kt + 1, 1 - s);
            CP_COMMIT();
        }
        uint32_t base = sb + STG_O + (uint32_t)s * 18432;

        // ---- S = Q K^T (single pass) ----
        float sc[8][4];
#pragma unroll
        for (int i = 0; i < 8; i++)
#pragma unroll
            for (int j = 0; j < 4; j++) sc[i][j] = 0.0f;

#pragma unroll
        for (int ks = 0; ks < 4; ks++) {
            uint32_t ahr[4];
            ldsm_x4(ahr, qa0 + ks * 32);
#pragma unroll
            for (int nfp = 0; nfp < 4; nfp++) {
                uint32_t k4[4];
                ldsm_x4(k4, base + bsel + (uint32_t)(nfp * 16 * ARB + ks * 32));
                mma_f16(sc[2 * nfp],     ahr, k4);
                mma_f16(sc[2 * nfp + 1], ahr, k4 + 2);
            }
        }

        // ---- causal mask + scale into log2 domain ----
        if (kt >= 2 * qt) {
#pragma unroll
            for (int nf = 0; nf < 8; nf++) {
                int gc = kt * 64 + nf * 8 + 2 * (l & 3);
                if (gc     > grow0) sc[nf][0] = -1e30f;
                if (gc + 1 > grow0) sc[nf][1] = -1e30f;
                if (gc     > grow1) sc[nf][2] = -1e30f;
                if (gc + 1 > grow1) sc[nf][3] = -1e30f;
            }
        }
#pragma unroll
        for (int nf = 0; nf < 8; nf++) {
            sc[nf][0] *= SCALE_LOG2E; sc[nf][1] *= SCALE_LOG2E;
            sc[nf][2] *= SCALE_LOG2E; sc[nf][3] *= SCALE_LOG2E;
        }

        // ---- online softmax ----
        float mx0 = -1e30f, mx1 = -1e30f;
#pragma unroll
        for (int nf = 0; nf < 8; nf++) {
            mx0 = fmaxf(mx0, fmaxf(sc[nf][0], sc[nf][1]));
            mx1 = fmaxf(mx1, fmaxf(sc[nf][2], sc[nf][3]));
        }
#pragma unroll
        for (int off = 1; off < 4; off <<= 1) {
            mx0 = fmaxf(mx0, __shfl_xor_sync(0xffffffffu, mx0, off));
            mx1 = fmaxf(mx1, __shfl_xor_sync(0xffffffffu, mx1, off));
        }
        float mn0 = fmaxf(m0, mx0), mn1 = fmaxf(m1, mx1);
        float al0 = fexp2(m0 - mn0), al1 = fexp2(m1 - mn1);
        m0 = mn0; m1 = mn1;

        float rs0 = 0.0f, rs1 = 0.0f;
#pragma unroll
        for (int nf = 0; nf < 8; nf++) {
            sc[nf][0] = fexp2(sc[nf][0] - mn0);
            sc[nf][1] = fexp2(sc[nf][1] - mn0);
            sc[nf][2] = fexp2(sc[nf][2] - mn1);
            sc[nf][3] = fexp2(sc[nf][3] - mn1);
            rs0 += sc[nf][0] + sc[nf][1];
            rs1 += sc[nf][2] + sc[nf][3];
        }
#pragma unroll
        for (int off = 1; off < 4; off <<= 1) {
            rs0 += __shfl_xor_sync(0xffffffffu, rs0, off);
            rs1 += __shfl_xor_sync(0xffffffffu, rs1, off);
        }
        l0 = l0 * al0 + rs0;
        l1 = l1 * al1 + rs1;
#pragma unroll
        for (int nf = 0; nf < 8; nf++) {
            o[nf][0] *= al0; o[nf][1] *= al0;
            o[nf][2] *= al1; o[nf][3] *= al1;
        }

        // ---- pack P (fp16) ----
        uint32_t ph[4][4];
#pragma unroll
        for (int ks = 0; ks < 4; ks++) {
            ph[ks][0] = pack_h2(sc[2 * ks][0],     sc[2 * ks][1]);
            ph[ks][1] = pack_h2(sc[2 * ks][2],     sc[2 * ks][3]);
            ph[ks][2] = pack_h2(sc[2 * ks + 1][0], sc[2 * ks + 1][1]);
            ph[ks][3] = pack_h2(sc[2 * ks + 1][2], sc[2 * ks + 1][3]);
        }

        // ---- O += P V (single pass) ----
#pragma unroll
        for (int ks = 0; ks < 4; ks++) {
#pragma unroll
            for (int np = 0; np < 4; np++) {
                uint32_t v4[4];
                ldsm_x4(v4, base + V_O + bsel + (uint32_t)(np * 16 * ARB + ks * 32));
                mma_f16(o[2 * np],     ph[ks], v4);
                mma_f16(o[2 * np + 1], ph[ks], v4 + 2);
            }
        }
    }

    // ---- write O as fp16 ----
    const int b = bh >> 4, h = bh & 15;
    float inv0 = 1.0f / l0, inv1 = 1.0f / l1;
    size_t r0 = (size_t)(b * S_ + grow0) * (H_ * DH) + h * DH;
    size_t r1 = (size_t)(b * S_ + grow1) * (H_ * DH) + h * DH;
#pragma unroll
    for (int nf = 0; nf < 8; nf++) {
        int e = nf * 8 + 2 * (l & 3);
        *(uint32_t*)&g_atth[r0 + e] = pack_h2(o[nf][0] * inv0, o[nf][1] * inv0);
        *(uint32_t*)&g_atth[r1 + e] = pack_h2(o[nf][2] * inv1, o[nf][3] * inv1);
    }
}

// ============================================================================
// O-projection via fp16 mma: out[8192,64] = att[8192,1024] @ Wo + bo
// 128x64 tile, BK=32, 3-stage pipeline, 8 warps (2m x 4n), warp tile 64x16.
// ============================================================================
#define OP_BW    10240
#define OP_STAGE 15360       // A 10240 + B 5120

__global__ __launch_bounds__(256) void oproj_mma_kernel(
    const float* __restrict__ bo, float* __restrict__ out)
{
    extern __shared__ __align__(128) char smem[];
    const uint32_t sb0 = smem_u32(smem);
    const int tid = threadIdx.x;
    const int wid = tid >> 5, l = tid & 31;
    const int wm = wid & 1, wn = wid >> 1;
    const int bm = blockIdx.x;
    const int arow0 = bm * 128;

    uint32_t aoff[4], boff;
#pragma unroll
    for (int mi = 0; mi < 4; mi++) {
        int row = wm * 64 + mi * 16 + (l & 15);
        int col = ((l >> 4) & 1) * 8;
        aoff[mi] = (uint32_t)(row * ROWB + col * 2);
    }
    {
        int nrow = wn * 16 + ((l >> 4) & 1) * 8 + (l & 7);
        int col = ((l >> 3) & 1) * 8;
        boff = (uint32_t)(nrow * ROWB + col * 2);
    }

    float acc[4][2][4];
#pragma unroll
    for (int i = 0; i < 4; i++)
#pragma unroll
        for (int j = 0; j < 2; j++)
#pragma unroll
            for (int q = 0; q < 4; q++) acc[i][j][q] = 0.0f;

    auto load_chunk = [&](int c, int s) {
        uint32_t base = sb0 + (uint32_t)s * OP_STAGE;
#pragma unroll
        for (int i = 0; i < 2; i++) {
            int slot = tid + i * 256;
            int row = slot >> 2, kg = slot & 3;
            uint32_t so = (uint32_t)(row * ROWB + kg * 16);
            cp16(base + so, g_atth + (size_t)(arow0 + row) * DIN + c * BK + kg * 8);
        }
        {
            int row = tid >> 2, kg = tid & 3;   // 64 rows of Wo^T
            uint32_t so = (uint32_t)(row * ROWB + kg * 16);
            cp16(base + OP_BW + so, g_woh + (size_t)row * DIN + c * BK + kg * 8);
        }
    };

    load_chunk(0, 0);
    CP_COMMIT();
    load_chunk(1, 1);
    CP_COMMIT();

    for (int c = 0; c < NCHUNK; c++) {
        int s = c % 3;
        if (c == NCHUNK - 1) { CP_WAIT(0); } else { CP_WAIT(1); }
        __syncthreads();

        uint32_t base = sb0 + (uint32_t)s * OP_STAGE;
#pragma unroll
        for (int ks = 0; ks < 2; ks++) {
            uint32_t kadd = (uint32_t)(ks * 32);
            uint32_t ah[4][4], bw[2][2];
#pragma unroll
            for (int mi = 0; mi < 4; mi++)
                ldsm_x4(ah[mi], base + aoff[mi] + kadd);
            {
                uint32_t r[4];
                ldsm_x4(r, base + OP_BW + boff + kadd);
                bw[0][0] = r[0]; bw[0][1] = r[1];
                bw[1][0] = r[2]; bw[1][1] = r[3];
            }
#pragma unroll
            for (int mi = 0; mi < 4; mi++)
#pragma unroll
                for (int ni = 0; ni < 2; ni++)
                    mma_f16(acc[mi][ni], ah[mi], bw[ni]);
        }

        if (c + 2 < NCHUNK) {
            load_chunk(c + 2, (c + 2) % 3);
            CP_COMMIT();
        }
    }

#pragma unroll
    for (int mi = 0; mi < 4; mi++) {
        int m0 = arow0 + wm * 64 + mi * 16 + (l >> 2);
#pragma unroll
        for (int ni = 0; ni < 2; ni++) {
            int ncol = wn * 16 + ni * 8 + 2 * (l & 3);
            float b0 = bo[ncol], b1 = bo[ncol + 1];
#pragma unroll
            for (int half = 0; half < 2; half++) {
                int m = m0 + half * 8;
                float2 v;
                v.x = acc[mi][ni][half * 2 + 0] + b0;
                v.y = acc[mi][ni][half * 2 + 1] + b1;
                *(float2*)&out[(size_t)m * DH + ncol] = v;
            }
        }
    }
}

// ============================================================================
extern "C" void kernel_launch(void* const* d_in, const int* in_sizes, int n_in,
                              void* d_out, int out_size)
{
    const float* x  = (const float*)d_in[0];
    const float* Wq = (const float*)d_in[1];
    const float* bq = (const float*)d_in[2];
    const float* Wk = (const float*)d_in[3];
    const float* bk = (const float*)d_in[4];
    const float* Wv = (const float*)d_in[5];
    const float* bv = (const float*)d_in[6];
    const float* Wo = (const float*)d_in[7];
    const float* bo = (const float*)d_in[8];
    float* out = (float*)d_out;

    cudaFuncSetAttribute(qkv_mma_kernel, cudaFuncAttributeMaxDynamicSharedMemorySize,
                         3 * STAGE_B);
    cudaFuncSetAttribute(attn_mma_kernel, cudaFuncAttributeMaxDynamicSharedMemorySize,
                         ATT_SMEM);
    cudaFuncSetAttribute(oproj_mma_kernel, cudaFuncAttributeMaxDynamicSharedMemorySize,
                         3 * OP_STAGE);

    cvt_x_kernel<<<8192, 256>>>(x);
    cvt_w_kernel<<<12544, 256>>>(Wq, Wk, Wv, Wo);
    qkv_mma_kernel<<<dim3(64, 24), 256, 3 * STAGE_B>>>(bq, bk, bv);
    vt_kernel<<<dim3(64, 64), 256>>>();
    attn_mma_kernel<<<dim3(16, 64), 256, ATT_SMEM>>>();
    oproj_mma_kernel<<<M_ / 128, 256, 3 * OP_STAGE>>>(bo, out);
}

// round 7
// speedup vs baseline: 6.4609x; 1.1679x over previous
#include <cuda_runtime.h>
#include <cuda_fp16.h>
#include <math.h>
#include <stdint.h>

#define B_   4
#define S_   2048
#define DIN  1024
#define H_   16
#define DH   64
#define M_   (B_ * S_)       // 8192
#define NTOT 3072
#define BH_  (B_ * H_)       // 64

// ---- scratch (device globals: allocation-free) ----
__device__ __half g_atth[M_ * H_ * DH];     // fp16 attention output [B*S, H*DH]

// fp16 attention operands, all [bh][s][e]
__device__ __half a_qh[BH_ * S_ * DH];
__device__ __half a_kh[BH_ * S_ * DH];
__device__ __half a_vh[BH_ * S_ * DH];

// fp16 operands for QKV GEMM / O-proj
__device__ __half g_xh[M_ * DIN];
__device__ __half g_wh[NTOT * DIN];         // [n][k]
__device__ __half g_woh[DH * DIN];          // [n][k] for O-proj (n=64)

#define SCALE_LOG2E 0.18033688011112042591999058f  // 0.125 * log2(e)

// ============================================================================
// helpers
// ============================================================================
__device__ __forceinline__ uint32_t smem_u32(const void* p) {
    uint32_t a;
    asm("{ .reg .u64 t; cvta.to.shared.u64 t, %1; cvt.u32.u64 %0, t; }"
        : "=r"(a) : "l"(p));
    return a;
}
__device__ __forceinline__ void cp16(uint32_t dst, const void* src) {
    asm volatile("cp.async.cg.shared.global [%0], [%1], 16;" :: "r"(dst), "l"(src));
}
#define CP_COMMIT() asm volatile("cp.async.commit_group;" ::: "memory")
#define CP_WAIT(n)  asm volatile("cp.async.wait_group %0;" :: "n"(n) : "memory")

__device__ __forceinline__ void ldsm_x4(uint32_t* r, uint32_t addr) {
    asm volatile("ldmatrix.sync.aligned.m8n8.x4.shared.b16 {%0,%1,%2,%3}, [%4];"
                 : "=r"(r[0]), "=r"(r[1]), "=r"(r[2]), "=r"(r[3]) : "r"(addr));
}
__device__ __forceinline__ void ldsm_x4_t(uint32_t* r, uint32_t addr) {
    asm volatile("ldmatrix.sync.aligned.m8n8.x4.trans.shared.b16 {%0,%1,%2,%3}, [%4];"
                 : "=r"(r[0]), "=r"(r[1]), "=r"(r[2]), "=r"(r[3]) : "r"(addr));
}
__device__ __forceinline__ void mma_f16(float* c, const uint32_t* a, const uint32_t* b) {
    asm volatile(
        "mma.sync.aligned.m16n8k16.row.col.f32.f16.f16.f32 "
        "{%0,%1,%2,%3}, {%4,%5,%6,%7}, {%8,%9}, {%0,%1,%2,%3};"
        : "+f"(c[0]), "+f"(c[1]), "+f"(c[2]), "+f"(c[3])
        : "r"(a[0]), "r"(a[1]), "r"(a[2]), "r"(a[3]), "r"(b[0]), "r"(b[1]));
}

// fast exp2 on FMA pipe (deg-5, rel err ~2e-6)
__device__ __forceinline__ float fexp2(float x) {
    x = fmaxf(x, -126.0f);
    int ni = __float2int_rn(x);
    float f = x - (float)ni;
    float p = 1.33336498e-3f;
    p = fmaf(p, f, 9.61804464e-3f);
    p = fmaf(p, f, 5.55036498e-2f);
    p = fmaf(p, f, 2.40226507e-1f);
    p = fmaf(p, f, 6.93147182e-1f);
    p = fmaf(p, f, 1.0f);
    return p * __int_as_float((ni + 127) << 23);
}

__device__ __forceinline__ uint32_t pack_h2(float x, float y) {
    __half2 h = __floats2half2_rn(x, y);
    return *(uint32_t*)&h;
}

// ============================================================================
// conversion kernels
// ============================================================================
__global__ __launch_bounds__(256) void cvt_x_kernel(const float* __restrict__ x) {
    int i = (blockIdx.x * 256 + threadIdx.x) * 4;
    float4 v = *(const float4*)&x[i];
    *(uint32_t*)&g_xh[i]     = pack_h2(v.x, v.y);
    *(uint32_t*)&g_xh[i + 2] = pack_h2(v.z, v.w);
}

// Coalesced transposing weight conversion.
// Blocks: bid = g*16 + kc; g<48: (part,h) of Wq/Wk/Wv; g==48: Wo.
// Each block transposes a 64(k) x 64(n) fp32 tile to [n][k] fp16.
__global__ __launch_bounds__(256) void cvt_w_kernel(
    const float* __restrict__ Wq, const float* __restrict__ Wk,
    const float* __restrict__ Wv, const float* __restrict__ Wo) {
    __shared__ float t[64][65];
    const int tid = threadIdx.x;
    const int bid = blockIdx.x;
    const int kc = bid & 15, g = bid >> 4;

    const float* src;
    __half* dst;
    if (g < 48) {
        int part = g >> 4, h = g & 15;
        const float* Wp = (part == 0) ? Wq : (part == 1) ? Wk : Wv;
        src = Wp + (size_t)h * (DIN * DH) + (size_t)kc * 64 * DH;
        dst = g_wh + (size_t)(part * 1024 + h * 64) * DIN + kc * 64;
    } else {
        src = Wo + (size_t)kc * 64 * DH;
        dst = g_woh + kc * 64;
    }

#pragma unroll
    for (int i = 0; i < 16; i++) {
        int idx = tid + i * 256;
        int kk = idx >> 6, e = idx & 63;
        t[kk][e] = src[kk * DH + e];
    }
    __syncthreads();
#pragma unroll
    for (int i = 0; i < 16; i++) {
        int idx = tid + i * 256;
        int e = idx >> 6, kk = idx & 63;
        dst[(size_t)e * DIN + kk] = __float2half_rn(t[kk][e]);
    }
}

// ============================================================================
// QKV GEMM, single-pass fp16 mma. 128x128 tile, BK=32, 3-stage pipeline.
// Epilogue writes Q/K/V all as fp16 [bh][s][e].
// ============================================================================
#define BK      32
#define NCHUNK  (DIN / BK)
#define ROWB    80
#define B_W     10240
#define STAGE_B 20480

__global__ __launch_bounds__(256) void qkv_mma_kernel(
    const float* __restrict__ bq, const float* __restrict__ bk,
    const float* __restrict__ bv)
{
    extern __shared__ __align__(128) char smem[];
    const uint32_t sb0 = smem_u32(smem);
    const int tid = threadIdx.x;
    const int wid = tid >> 5, l = tid & 31;
    const int wm = wid & 1, wn = wid >> 1;
    const int bm = blockIdx.x;
    const int bn = blockIdx.y;

    const int arow0 = bm * 128, brow0 = bn * 128;

    uint32_t aoff[4], boff[2];
#pragma unroll
    for (int mi = 0; mi < 4; mi++) {
        int row = wm * 64 + mi * 16 + (l & 15);
        int col = ((l >> 4) & 1) * 8;
        aoff[mi] = (uint32_t)(row * ROWB + col * 2);
    }
#pragma unroll
    for (int bg = 0; bg < 2; bg++) {
        int nrow = wn * 32 + bg * 16 + ((l >> 4) & 1) * 8 + (l & 7);
        int col = ((l >> 3) & 1) * 8;
        boff[bg] = (uint32_t)(nrow * ROWB + col * 2);
    }

    float acc[4][4][4];
#pragma unroll
    for (int i = 0; i < 4; i++)
#pragma unroll
        for (int j = 0; j < 4; j++)
#pragma unroll
            for (int q = 0; q < 4; q++) acc[i][j][q] = 0.0f;

    auto load_chunk = [&](int c, int s) {
        uint32_t base = sb0 + (uint32_t)s * STAGE_B;
#pragma unroll
        for (int i = 0; i < 2; i++) {
            int slot = tid + i * 256;
            int row = slot >> 2, kg = slot & 3;
            uint32_t so = (uint32_t)(row * ROWB + kg * 16);
            cp16(base + so,       g_xh + (size_t)(arow0 + row) * DIN + c * BK + kg * 8);
            cp16(base + B_W + so, g_wh + (size_t)(brow0 + row) * DIN + c * BK + kg * 8);
        }
    };

    load_chunk(0, 0);
    CP_COMMIT();
    load_chunk(1, 1);
    CP_COMMIT();

    for (int c = 0; c < NCHUNK; c++) {
        int s = c % 3;
        if (c == NCHUNK - 1) { CP_WAIT(0); } else { CP_WAIT(1); }
        __syncthreads();

        uint32_t base = sb0 + (uint32_t)s * STAGE_B;
#pragma unroll
        for (int ks = 0; ks < 2; ks++) {
            uint32_t kadd = (uint32_t)(ks * 32);
            uint32_t ah[4][4], bw[4][2];
#pragma unroll
            for (int mi = 0; mi < 4; mi++)
                ldsm_x4(ah[mi], base + aoff[mi] + kadd);
#pragma unroll
            for (int bg = 0; bg < 2; bg++) {
                uint32_t r[4];
                ldsm_x4(r, base + B_W + boff[bg] + kadd);
                bw[bg * 2][0] = r[0]; bw[bg * 2][1] = r[1];
                bw[bg * 2 + 1][0] = r[2]; bw[bg * 2 + 1][1] = r[3];
            }
#pragma unroll
            for (int mi = 0; mi < 4; mi++)
#pragma unroll
                for (int ni = 0; ni < 4; ni++)
                    mma_f16(acc[mi][ni], ah[mi], bw[ni]);
        }

        if (c + 2 < NCHUNK) {
            load_chunk(c + 2, (c + 2) % 3);
            CP_COMMIT();
        }
    }

    const int part = bn >> 3;
    const float* __restrict__ bp = (part == 0) ? bq : (part == 1) ? bk : bv;
    __half* __restrict__ oh = (part == 0) ? a_qh : (part == 1) ? a_kh : a_vh;
    const int npart0 = (bn & 7) * 128 + wn * 32;

#pragma unroll
    for (int mi = 0; mi < 4; mi++) {
        int m0 = arow0 + wm * 64 + mi * 16 + (l >> 2);
#pragma unroll
        for (int ni = 0; ni < 4; ni++) {
            int ncol = npart0 + ni * 8 + 2 * (l & 3);
            int h = ncol >> 6, e = ncol & 63;
            float b0 = bp[h * DH + e], b1 = bp[h * DH + e + 1];
#pragma unroll
            for (int half = 0; half < 2; half++) {
                int m = m0 + half * 8;
                int bb = m >> 11, sIdx = m & 2047;
                float v0 = acc[mi][ni][half * 2 + 0] + b0;
                float v1 = acc[mi][ni][half * 2 + 1] + b1;
                size_t idx = (((size_t)bb * H_ + h) * S_ + sIdx) * DH + e;
                *(uint32_t*)&oh[idx] = pack_h2(v0, v1);
            }
        }
    }
}

// ============================================================================
// Causal flash attention, single-pass fp16 mma.
// K and V tiles both stored [s][e]; V fragments via ldmatrix.trans.
// Heavy q-tiles scheduled first (qt = 15 - blockIdx.y).
// ============================================================================
#define ARB    144
#define Q_O    0
#define STG_O  18432           // stage size 18432: K | V
#define V_O    9216
#define ATT_SMEM (18432 + 2 * 18432)

__global__ __launch_bounds__(256, 1) void attn_mma_kernel()
{
    extern __shared__ __align__(128) char smem[];
    const uint32_t sb = smem_u32(smem);
    const int tid = threadIdx.x;
    const int w = tid >> 5, l = tid & 31;
    const int bh = blockIdx.x;        // 0..63
    const int qt = 15 - blockIdx.y;   // heavy tiles first

    const __half* __restrict__ qh = a_qh + (size_t)bh * S_ * DH;
    const __half* __restrict__ kh = a_kh + (size_t)bh * S_ * DH;
    const __half* __restrict__ vh = a_vh + (size_t)bh * S_ * DH;

    // ---- load Q tile (128x64) ----
#pragma unroll
    for (int i = 0; i < 4; i++) {
        int idx = tid + i * 256;
        int row = idx >> 3, kg = idx & 7;
        uint32_t so = (uint32_t)(row * ARB + kg * 16);
        cp16(sb + Q_O + so, qh + (size_t)(qt * 128 + row) * DH + kg * 8);
    }

    auto load_kv = [&](int kt, int s) {
        uint32_t base = sb + STG_O + (uint32_t)s * 18432;
#pragma unroll
        for (int i = 0; i < 2; i++) {
            int idx = tid + i * 256;
            int row = idx >> 3, kg = idx & 7;
            uint32_t so = (uint32_t)(row * ARB + kg * 16);
            size_t go = (size_t)(kt * 64 + row) * DH + kg * 8;
            cp16(base + so,       kh + go);
            cp16(base + V_O + so, vh + go);
        }
    };

    const int nkt = 2 * qt + 2;
    load_kv(0, 0);
    CP_COMMIT();

    float o[8][4];
#pragma unroll
    for (int i = 0; i < 8; i++)
#pragma unroll
        for (int j = 0; j < 4; j++) o[i][j] = 0.0f;
    float m0 = -1e30f, m1 = -1e30f, l0 = 0.0f, l1 = 0.0f;

    const int grow0 = qt * 128 + w * 16 + (l >> 2);
    const int grow1 = grow0 + 8;
    const uint32_t qa0 = sb + Q_O + (uint32_t)((w * 16 + (l & 15)) * ARB
                                               + ((l >> 4) & 1) * 16);
    const uint32_t bsel = (uint32_t)((8 * ((l >> 4) & 1) + (l & 7)) * ARB
                                     + ((l >> 3) & 1) * 16);
    // V (trans) lane address: s-row from l&7 + bit3, e-half from bit4
    const uint32_t vsel = (uint32_t)(((((l >> 3) & 1) * 8) + (l & 7)) * ARB
                                     + ((l >> 4) & 1) * 16);

    for (int kt = 0; kt < nkt; kt++) {
        int s = kt & 1;
        CP_WAIT(0);
        __syncthreads();
        if (kt + 1 < nkt) {
            load_kv(kt + 1, 1 - s);
            CP_COMMIT();
        }
        uint32_t base = sb + STG_O + (uint32_t)s * 18432;

        // ---- S = Q K^T ----
        float sc[8][4];
#pragma unroll
        for (int i = 0; i < 8; i++)
#pragma unroll
            for (int j = 0; j < 4; j++) sc[i][j] = 0.0f;

#pragma unroll
        for (int ks = 0; ks < 4; ks++) {
            uint32_t ahr[4];
            ldsm_x4(ahr, qa0 + ks * 32);
#pragma unroll
            for (int nfp = 0; nfp < 4; nfp++) {
                uint32_t k4[4];
                ldsm_x4(k4, base + bsel + (uint32_t)(nfp * 16 * ARB + ks * 32));
                mma_f16(sc[2 * nfp],     ahr, k4);
                mma_f16(sc[2 * nfp + 1], ahr, k4 + 2);
            }
        }

        // ---- causal mask + scale into log2 domain ----
        if (kt >= 2 * qt) {
#pragma unroll
            for (int nf = 0; nf < 8; nf++) {
                int gc = kt * 64 + nf * 8 + 2 * (l & 3);
                if (gc     > grow0) sc[nf][0] = -1e30f;
                if (gc + 1 > grow0) sc[nf][1] = -1e30f;
                if (gc     > grow1) sc[nf][2] = -1e30f;
                if (gc + 1 > grow1) sc[nf][3] = -1e30f;
            }
        }
#pragma unroll
        for (int nf = 0; nf < 8; nf++) {
            sc[nf][0] *= SCALE_LOG2E; sc[nf][1] *= SCALE_LOG2E;
            sc[nf][2] *= SCALE_LOG2E; sc[nf][3] *= SCALE_LOG2E;
        }

        // ---- online softmax ----
        float mx0 = -1e30f, mx1 = -1e30f;
#pragma unroll
        for (int nf = 0; nf < 8; nf++) {
            mx0 = fmaxf(mx0, fmaxf(sc[nf][0], sc[nf][1]));
            mx1 = fmaxf(mx1, fmaxf(sc[nf][2], sc[nf][3]));
        }
#pragma unroll
        for (int off = 1; off < 4; off <<= 1) {
            mx0 = fmaxf(mx0, __shfl_xor_sync(0xffffffffu, mx0, off));
            mx1 = fmaxf(mx1, __shfl_xor_sync(0xffffffffu, mx1, off));
        }
        float mn0 = fmaxf(m0, mx0), mn1 = fmaxf(m1, mx1);
        float al0 = fexp2(m0 - mn0), al1 = fexp2(m1 - mn1);
        m0 = mn0; m1 = mn1;

        float rs0 = 0.0f, rs1 = 0.0f;
#pragma unroll
        for (int nf = 0; nf < 8; nf++) {
            sc[nf][0] = fexp2(sc[nf][0] - mn0);
            sc[nf][1] = fexp2(sc[nf][1] - mn0);
            sc[nf][2] = fexp2(sc[nf][2] - mn1);
            sc[nf][3] = fexp2(sc[nf][3] - mn1);
            rs0 += sc[nf][0] + sc[nf][1];
            rs1 += sc[nf][2] + sc[nf][3];
        }
#pragma unroll
        for (int off = 1; off < 4; off <<= 1) {
            rs0 += __shfl_xor_sync(0xffffffffu, rs0, off);
            rs1 += __shfl_xor_sync(0xffffffffu, rs1, off);
        }
        l0 = l0 * al0 + rs0;
        l1 = l1 * al1 + rs1;
#pragma unroll
        for (int nf = 0; nf < 8; nf++) {
            o[nf][0] *= al0; o[nf][1] *= al0;
            o[nf][2] *= al1; o[nf][3] *= al1;
        }

        // ---- pack P (fp16) ----
        uint32_t ph[4][4];
#pragma unroll
        for (int ks = 0; ks < 4; ks++) {
            ph[ks][0] = pack_h2(sc[2 * ks][0],     sc[2 * ks][1]);
            ph[ks][1] = pack_h2(sc[2 * ks][2],     sc[2 * ks][3]);
            ph[ks][2] = pack_h2(sc[2 * ks + 1][0], sc[2 * ks + 1][1]);
            ph[ks][3] = pack_h2(sc[2 * ks + 1][2], sc[2 * ks + 1][3]);
        }

        // ---- O += P V : V fragments via transposing ldmatrix on [s][e] ----
#pragma unroll
        for (int ks = 0; ks < 4; ks++) {
#pragma unroll
            for (int np = 0; np < 4; np++) {
                uint32_t v4[4];
                ldsm_x4_t(v4, base + V_O + vsel
                              + (uint32_t)(ks * 16 * ARB + np * 32));
                mma_f16(o[2 * np],     ph[ks], v4);
                mma_f16(o[2 * np + 1], ph[ks], v4 + 2);
            }
        }
    }

    // ---- write O as fp16 ----
    const int b = bh >> 4, h = bh & 15;
    float inv0 = 1.0f / l0, inv1 = 1.0f / l1;
    size_t r0 = (size_t)(b * S_ + grow0) * (H_ * DH) + h * DH;
    size_t r1 = (size_t)(b * S_ + grow1) * (H_ * DH) + h * DH;
#pragma unroll
    for (int nf = 0; nf < 8; nf++) {
        int e = nf * 8 + 2 * (l & 3);
        *(uint32_t*)&g_atth[r0 + e] = pack_h2(o[nf][0] * inv0, o[nf][1] * inv0);
        *(uint32_t*)&g_atth[r1 + e] = pack_h2(o[nf][2] * inv1, o[nf][3] * inv1);
    }
}

// ============================================================================
// O-projection via fp16 mma: out[8192,64] = att[8192,1024] @ Wo + bo
// ============================================================================
#define OP_BW    10240
#define OP_STAGE 15360       // A 10240 + B 5120

__global__ __launch_bounds__(256) void oproj_mma_kernel(
    const float* __restrict__ bo, float* __restrict__ out)
{
    extern __shared__ __align__(128) char smem[];
    const uint32_t sb0 = smem_u32(smem);
    const int tid = threadIdx.x;
    const int wid = tid >> 5, l = tid & 31;
    const int wm = wid & 1, wn = wid >> 1;
    const int bm = blockIdx.x;
    const int arow0 = bm * 128;

    uint32_t aoff[4], boff;
#pragma unroll
    for (int mi = 0; mi < 4; mi++) {
        int row = wm * 64 + mi * 16 + (l & 15);
        int col = ((l >> 4) & 1) * 8;
        aoff[mi] = (uint32_t)(row * ROWB + col * 2);
    }
    {
        int nrow = wn * 16 + ((l >> 4) & 1) * 8 + (l & 7);
        int col = ((l >> 3) & 1) * 8;
        boff = (uint32_t)(nrow * ROWB + col * 2);
    }

    float acc[4][2][4];
#pragma unroll
    for (int i = 0; i < 4; i++)
#pragma unroll
        for (int j = 0; j < 2; j++)
#pragma unroll
            for (int q = 0; q < 4; q++) acc[i][j][q] = 0.0f;

    auto load_chunk = [&](int c, int s) {
        uint32_t base = sb0 + (uint32_t)s * OP_STAGE;
#pragma unroll
        for (int i = 0; i < 2; i++) {
            int slot = tid + i * 256;
            int row = slot >> 2, kg = slot & 3;
            uint32_t so = (uint32_t)(row * ROWB + kg * 16);
            cp16(base + so, g_atth + (size_t)(arow0 + row) * DIN + c * BK + kg * 8);
        }
        {
            int row = tid >> 2, kg = tid & 3;
            uint32_t so = (uint32_t)(row * ROWB + kg * 16);
            cp16(base + OP_BW + so, g_woh + (size_t)row * DIN + c * BK + kg * 8);
        }
    };

    load_chunk(0, 0);
    CP_COMMIT();
    load_chunk(1, 1);
    CP_COMMIT();

    for (int c = 0; c < NCHUNK; c++) {
        int s = c % 3;
        if (c == NCHUNK - 1) { CP_WAIT(0); } else { CP_WAIT(1); }
        __syncthreads();

        uint32_t base = sb0 + (uint32_t)s * OP_STAGE;
#pragma unroll
        for (int ks = 0; ks < 2; ks++) {
            uint32_t kadd = (uint32_t)(ks * 32);
            uint32_t ah[4][4], bw[2][2];
#pragma unroll
            for (int mi = 0; mi < 4; mi++)
                ldsm_x4(ah[mi], base + aoff[mi] + kadd);
            {
                uint32_t r[4];
                ldsm_x4(r, base + OP_BW + boff + kadd);
                bw[0][0] = r[0]; bw[0][1] = r[1];
                bw[1][0] = r[2]; bw[1][1] = r[3];
            }
#pragma unroll
            for (int mi = 0; mi < 4; mi++)
#pragma unroll
                for (int ni = 0; ni < 2; ni++)
                    mma_f16(acc[mi][ni], ah[mi], bw[ni]);
        }

        if (c + 2 < NCHUNK) {
            load_chunk(c + 2, (c + 2) % 3);
            CP_COMMIT();
        }
    }

#pragma unroll
    for (int mi = 0; mi < 4; mi++) {
        int m0 = arow0 + wm * 64 + mi * 16 + (l >> 2);
#pragma unroll
        for (int ni = 0; ni < 2; ni++) {
            int ncol = wn * 16 + ni * 8 + 2 * (l & 3);
            float b0 = bo[ncol], b1 = bo[ncol + 1];
#pragma unroll
            for (int half = 0; half < 2; half++) {
                int m = m0 + half * 8;
                float2 v;
                v.x = acc[mi][ni][half * 2 + 0] + b0;
                v.y = acc[mi][ni][half * 2 + 1] + b1;
                *(float2*)&out[(size_t)m * DH + ncol] = v;
            }
        }
    }
}

// ============================================================================
extern "C" void kernel_launch(void* const* d_in, const int* in_sizes, int n_in,
                              void* d_out, int out_size)
{
    const float* x  = (const float*)d_in[0];
    const float* Wq = (const float*)d_in[1];
    const float* bq = (const float*)d_in[2];
    const float* Wk = (const float*)d_in[3];
    const float* bk = (const float*)d_in[4];
    const float* Wv = (const float*)d_in[5];
    const float* bv = (const float*)d_in[6];
    const float* Wo = (const float*)d_in[7];
    const float* bo = (const float*)d_in[8];
    float* out = (float*)d_out;

    cudaFuncSetAttribute(qkv_mma_kernel, cudaFuncAttributeMaxDynamicSharedMemorySize,
                         3 * STAGE_B);
    cudaFuncSetAttribute(attn_mma_kernel, cudaFuncAttributeMaxDynamicSharedMemorySize,
                         ATT_SMEM);
    cudaFuncSetAttribute(oproj_mma_kernel, cudaFuncAttributeMaxDynamicSharedMemorySize,
                         3 * OP_STAGE);

    cvt_x_kernel<<<8192, 256>>>(x);
    cvt_w_kernel<<<784, 256>>>(Wq, Wk, Wv, Wo);
    qkv_mma_kernel<<<dim3(64, 24), 256, 3 * STAGE_B>>>(bq, bk, bv);
    attn_mma_kernel<<<dim3(64, 16), 256, ATT_SMEM>>>();
    oproj_mma_kernel<<<M_ / 128, 256, 3 * OP_STAGE>>>(bo, out);
}